// round 5
// baseline (speedup 1.0000x reference)
#include <cuda_runtime.h>
#include <cuda_fp16.h>
#include <math.h>

#define NSTEP 256
#define G 4
#define NCTA 128
#define NTHREADS 512

// fp16 W1, re-tiled: [unit(366)][j(64)][kkk(8)]; unit = m*18+qq for m=0..19,
// units 360..365 are zero padding (GEMM-B tail). k = qq*8+kkk, pad k>=129 -> 0
#define W1H_UNITS 366
#define W1H_ELEMS (W1H_UNITS*64*8)
__device__ __half g_W1h[W1H_ELEMS];

// ---- shared memory layout (float offsets) ----
// ring row = 144 floats (36 float4): [0..127]=nh, [128]=error, [129..143]=0
#define RING_OFF   0        // [4][20][144] = 11520
#define W1A_OFF    11520    // m=0 weights fp32 [33 q][64 j][4 kk] = 8448
#define WHH_OFF    19968    // [16 h'][8c*64gate] = 8192
#define WAIH_OFF   28160    // [2][16 k][64 gate] = 2048
#define WAHH_OFF   30208    // 2048
#define W2S_OFF    32256    // [16][65] = 1040
#define WIH_OFF    33296    // 512
#define BE_OFF     33808    // 512
#define PSB_OFF    34320    // GEMM-B partials [12 c][64 j][4 g] = 3072
#define OLDPS_OFF  37392    // [2 parity][64 j * 4 g] = 512
#define E1S_OFF    37904    // [4][64]
#define ZBUF_OFF   38160    // [4][64]
#define NC_OFF     38416    // [4][128]
#define B1S_OFF    38928    // 64
#define BAC_OFF    38992    // [2][64]
#define WGS_OFF    39120    // [8][16]
#define WOS_OFF    39248    // [8][16]
#define EHS_OFF    39376    // [4][16]
#define ECS_OFF    39440
#define AHS_OFF    39504    // [2][4][16]
#define ACS_OFF    39632
#define AIS_OFF    39760    // [4][16]
#define GSM_OFF    39824    // [4][8]
#define OSM_OFF    39856    // [4][8]
#define ERRH_OFF   39888    // [4][10]
#define B2S_OFF    39928
#define BGS_OFF    39944
#define BOS_OFF    39952
#define PRED_OFF   39960
#define THETA_OFF  39964
#define SMEM_FLOATS 39968
#define SMEM_BYTES  (SMEM_FLOATS * 4)

__device__ __forceinline__ float sigf(float v) {
    return __fdividef(1.0f, 1.0f + __expf(-v));
}

#define FMA2(acc, a, b) \
    asm("fma.rn.f32x2 %0, %1, %2, %0;" : "+l"(acc) : "l"(a), "l"(b))

__device__ __forceinline__ float pair_sum(unsigned long long v) {
    union { unsigned long long u; float2 f; } cv; cv.u = v;
    return cv.f.x + cv.f.y;
}

__device__ __forceinline__ unsigned long long h2f2(unsigned int h2) {
    union { float2 f; unsigned long long u; } cv;
    cv.f = __half22float2(*reinterpret_cast<const __half2*>(&h2));
    return cv.u;
}

__global__ void build_w1h(const float* __restrict__ W1) {
    int idx = blockIdx.x * 256 + threadIdx.x;
    if (idx >= W1H_ELEMS) return;
    int kkk = idx & 7;
    int f8  = idx >> 3;
    int j   = f8 & 63;
    int mu  = f8 >> 6;          // unit in [0,366)
    float v = 0.0f;
    if (mu < 360) {
        int m  = mu / 18;
        int qq = mu - m * 18;
        int k  = qq * 8 + kkk;
        if (k < 129) v = W1[j * 2580 + m * 129 + k];
    }
    g_W1h[idx] = __float2half(v);
}

__global__ __launch_bounds__(NTHREADS, 1)
void mmoe_main(
    const float* __restrict__ x,      const float* __restrict__ pred0,
    const float* __restrict__ gate0,
    const float* __restrict__ W_ih,   const float* __restrict__ W_hh,
    const float* __restrict__ b_ih,   const float* __restrict__ b_hh,
    const float* __restrict__ W_o,    const float* __restrict__ b_o,
    const float* __restrict__ W1,     const float* __restrict__ b1,
    const float* __restrict__ W2,     const float* __restrict__ b2,
    const float* __restrict__ Wg,     const float* __restrict__ bg,
    const float* __restrict__ Wa_ih,  const float* __restrict__ Wa_hh,
    const float* __restrict__ ba_ih,  const float* __restrict__ ba_hh,
    float* __restrict__ out)
{
    extern __shared__ float sm[];
    const int tid = threadIdx.x;
    const int b0  = blockIdx.x * G;

    // ---------- init shared ----------
    for (int i = tid; i < 11520; i += NTHREADS) {
        int pos = i % 144;
        sm[RING_OFF + i] = (pos == 128) ? 0.5f : 0.0f;
    }
    for (int i = tid; i < 8448; i += NTHREADS) {
        int kk = i & 3, jj = (i >> 2) & 63, q = i >> 8;
        int k = q * 4 + kk;
        sm[W1A_OFF + i] = (k < 129) ? W1[jj * 2580 + k] : 0.0f;
    }
    for (int i = tid; i < 8192; i += NTHREADS) {
        int h = i >> 9, cg = i & 511;
        sm[WHH_OFF + i] = W_hh[cg * 16 + h];
    }
    for (int i = tid; i < 2048; i += NTHREADS) {
        int l = i >> 10, r = i & 1023, k = r >> 6, gate = r & 63;
        sm[WAIH_OFF + i] = Wa_ih[l * 1024 + gate * 16 + k];
        sm[WAHH_OFF + i] = Wa_hh[l * 1024 + gate * 16 + k];
    }
    for (int i = tid; i < 1040; i += NTHREADS) {
        int j2 = i / 65, k = i - j2 * 65;
        sm[W2S_OFF + i] = (k < 64) ? W2[j2 * 64 + k] : 0.0f;
    }
    if (tid < 512) {
        sm[WIH_OFF + tid] = W_ih[tid];
        sm[BE_OFF + tid]  = b_ih[tid] + b_hh[tid];
    }
    if (tid < 256) {
        // initial old-rows partial: rows m=1..19 are (0,...,0, 0.5)
        int jj = tid >> 2, gg = tid & 3;
        float sacc = 0.0f;
        for (int m = 1; m < 20; ++m) sacc += W1[jj * 2580 + m * 129 + 128];
        sm[OLDPS_OFF + jj * 4 + gg] = 0.5f * sacc;
    }
    if (tid < 128) {
        sm[BAC_OFF + tid] = ba_ih[tid] + ba_hh[tid];
        sm[WGS_OFF + tid] = Wg[tid];
        sm[WOS_OFF + tid] = W_o[tid];
        sm[AHS_OFF + tid] = 0.0f;
        sm[ACS_OFF + tid] = 0.0f;
    }
    if (tid < 64) { sm[B1S_OFF + tid] = b1[tid]; sm[EHS_OFF + tid] = 0.0f; sm[ECS_OFF + tid] = 0.0f; }
    if (tid < 40) sm[ERRH_OFF + tid] = 0.5f;
    if (tid < 32) sm[GSM_OFF + tid] = gate0[b0 * 8 + tid];
    if (tid < 16) sm[B2S_OFF + tid] = b2[tid];
    if (tid < 8)  { sm[BGS_OFF + tid] = bg[tid]; sm[BOS_OFF + tid] = b_o[tid]; }
    if (tid < 4)  sm[PRED_OFF + tid] = pred0[b0 + tid];
    __syncthreads();

    int head = 0;

    for (int t = 0; t < NSTEP; ++t) {
        int s = head - 1; if (s < 0) s = 19;   // nh_slot

        // ---- phase 2: experts (all 512 threads); error folded in ----
        {
            int g = tid >> 7, c = (tid >> 4) & 7, h = tid & 15;
            int cg = c << 6;
            float xv = __ldg(&x[(b0 + g) * NSTEP + t]);
            float zi = sm[BE_OFF + cg + h]      + xv * sm[WIH_OFF + cg + h];
            float zf = sm[BE_OFF + cg + 16 + h] + xv * sm[WIH_OFF + cg + 16 + h];
            float zg = sm[BE_OFF + cg + 32 + h] + xv * sm[WIH_OFF + cg + 32 + h];
            float zo = sm[BE_OFF + cg + 48 + h] + xv * sm[WIH_OFF + cg + 48 + h];
            #pragma unroll
            for (int k = 0; k < 16; ++k) {
                float ev = sm[EHS_OFF + g * 16 + k];
                const float* wr = &sm[WHH_OFF + k * 512 + cg];
                zi += ev * wr[h];
                zf += ev * wr[16 + h];
                zg += ev * wr[32 + h];
                zo += ev * wr[48 + h];
            }
            float c2 = sigf(zf) * sm[ECS_OFF + g * 16 + h] + sigf(zi) * tanhf(zg);
            float hn = sigf(zo) * tanhf(c2);
            sm[RING_OFF + (g * 20 + s) * 144 + c * 16 + h] = hn;
            sm[NC_OFF + g * 128 + c * 16 + h] = c2;
        }
        if (tid < 4) {
            float xv = x[(b0 + tid) * NSTEP + t];
            float e = xv - sm[PRED_OFF + tid];
            sm[ERRH_OFF + tid * 10 + (t % 10)] = e;
            sm[RING_OFF + (tid * 20 + s) * 144 + 128] = e;
        }
        __syncthreads();

        if (tid < 128) {
            // ================= small group: warps 0-3 =================
            // ---- GEMM-A: new-row slice (m=0) + old partial -> e1 ----
            {
                int jA = tid & 63, gp = tid >> 6;
                const float4* wA = reinterpret_cast<const float4*>(&sm[W1A_OFF]);
                const float4* r4 = reinterpret_cast<const float4*>(sm);
                int rb0 = ((2 * gp)     * 20 + s) * 36;
                int rb1 = ((2 * gp + 1) * 20 + s) * 36;
                float acc0 = 0.0f, acc1 = 0.0f;
                #pragma unroll 3
                for (int q = 0; q < 33; ++q) {
                    float4 w  = wA[q * 64 + jA];
                    float4 v0 = r4[rb0 + q];
                    acc0 += w.x * v0.x + w.y * v0.y + w.z * v0.z + w.w * v0.w;
                    float4 v1 = r4[rb1 + q];
                    acc1 += w.x * v1.x + w.y * v1.y + w.z * v1.z + w.w * v1.w;
                }
                int par = (t & 1) * 256;
                float bb = sm[B1S_OFF + jA];
                sm[E1S_OFF + (2 * gp) * 64 + jA] =
                    fmaxf(acc0 + sm[OLDPS_OFF + par + jA * 4 + 2 * gp] + bb, 0.0f);
                sm[E1S_OFF + (2 * gp + 1) * 64 + jA] =
                    fmaxf(acc1 + sm[OLDPS_OFF + par + jA * 4 + 2 * gp + 1] + bb, 0.0f);
            }
            asm volatile("bar.sync 1, 128;" ::: "memory");

            // ---- phase 5: MLP2 | expert heads | theta ----
            if (tid < 64) {
                int g = tid >> 4, j2 = tid & 15;
                float sacc = sm[B2S_OFF + j2];
                #pragma unroll
                for (int k = 0; k < 64; ++k)
                    sacc += sm[E1S_OFF + g * 64 + k] * sm[W2S_OFF + j2 * 65 + k];
                sm[AIS_OFF + g * 16 + j2] = fmaxf(sacc, 0.0f);
            } else if (tid < 96) {
                int u = tid - 64, g = u >> 3, c = u & 7;
                float sacc = sm[BOS_OFF + c];
                const float* rr = &sm[RING_OFF + (g * 20 + s) * 144 + c * 16];
                #pragma unroll
                for (int h = 0; h < 16; ++h) sacc += rr[h] * sm[WOS_OFF + c * 16 + h];
                sm[OSM_OFF + g * 8 + c] = sacc;
            } else if (tid < 100) {
                int g = tid - 96;
                float sacc = 0.0f;
                #pragma unroll
                for (int i2 = 0; i2 < 10; ++i2) sacc += fabsf(sm[ERRH_OFF + g * 10 + i2]);
                sm[THETA_OFF + g] = fminf(0.25f * sacc, 1.0f);
            }
            asm volatile("bar.sync 1, 128;" ::: "memory");

            // ---- phase 6: agent, 2 stacked LSTM layers ----
            #pragma unroll 1
            for (int l = 0; l < 2; ++l) {
                #pragma unroll
                for (int r = 0; r < 2; ++r) {
                    int e = tid + (r << 7);
                    int g = e >> 6, gate = e & 63;
                    const float* inp = (l == 0) ? &sm[AIS_OFF + g * 16]
                                                : &sm[AHS_OFF + g * 16];
                    const float* hp  = &sm[AHS_OFF + l * 64 + g * 16];
                    float z = sm[BAC_OFF + l * 64 + gate];
                    const float* wi = &sm[WAIH_OFF + l * 1024 + gate];
                    const float* wh = &sm[WAHH_OFF + l * 1024 + gate];
                    #pragma unroll
                    for (int k = 0; k < 16; ++k)
                        z += inp[k] * wi[k * 64] + hp[k] * wh[k * 64];
                    sm[ZBUF_OFF + g * 64 + gate] = z;
                }
                asm volatile("bar.sync 1, 128;" ::: "memory");
                if (tid < 64) {
                    int g2 = tid >> 4, h = tid & 15;
                    float zi = sm[ZBUF_OFF + g2 * 64 + h];
                    float zf = sm[ZBUF_OFF + g2 * 64 + 16 + h];
                    float zg = sm[ZBUF_OFF + g2 * 64 + 32 + h];
                    float zo = sm[ZBUF_OFF + g2 * 64 + 48 + h];
                    float c2 = sigf(zf) * sm[ACS_OFF + l * 64 + g2 * 16 + h]
                             + sigf(zi) * tanhf(zg);
                    float hn = sigf(zo) * tanhf(c2);
                    sm[ACS_OFF + l * 64 + g2 * 16 + h] = c2;
                    sm[AHS_OFF + l * 64 + g2 * 16 + h] = hn;
                }
                asm volatile("bar.sync 1, 128;" ::: "memory");
            }

            // ---- phase 7a: gate logits ----
            if (tid < 32) {
                int g = tid >> 3, c = tid & 7;
                float sacc = sm[BGS_OFF + c];
                const float* a1p = &sm[AHS_OFF + 64 + g * 16];
                #pragma unroll
                for (int k = 0; k < 16; ++k) sacc += a1p[k] * sm[WGS_OFF + c * 16 + k];
                sm[ZBUF_OFF + g * 8 + c] = sacc;
            }
            asm volatile("bar.sync 1, 128;" ::: "memory");

            // ---- phase 7b: softmax + blend + pred ----
            if (tid < 4) {
                int g = tid;
                float mx = -1e30f;
                #pragma unroll
                for (int c = 0; c < 8; ++c) mx = fmaxf(mx, sm[ZBUF_OFF + g * 8 + c]);
                float ex[8], ssum = 0.0f;
                #pragma unroll
                for (int c = 0; c < 8; ++c) { ex[c] = __expf(sm[ZBUF_OFF + g * 8 + c] - mx); ssum += ex[c]; }
                float inv = __fdividef(1.0f, ssum);
                float th = sm[THETA_OFF + g];
                float pred = 0.0f;
                #pragma unroll
                for (int c = 0; c < 8; ++c) {
                    float gf = ex[c] * inv * th + sm[GSM_OFF + g * 8 + c] * (1.0f - th);
                    sm[GSM_OFF + g * 8 + c] = gf;
                    pred += gf * sm[OSM_OFF + g * 8 + c];
                }
                sm[PRED_OFF + g] = pred;
                out[(b0 + g) * NSTEP + t] = pred;
            }
            asm volatile("bar.sync 1, 128;" ::: "memory");

            // ---- phase 7c: eh2 / ec2 ----
            if (tid < 64) {
                int g = tid >> 4, h = tid & 15;
                const float* rr = &sm[RING_OFF + (g * 20 + s) * 144];
                const float* nc = &sm[NC_OFF + g * 128];
                float se = 0.0f, sc = 0.0f;
                #pragma unroll
                for (int c = 0; c < 8; ++c) {
                    float gf = sm[GSM_OFF + g * 8 + c];
                    se += gf * rr[c * 16 + h];
                    sc += gf * nc[c * 16 + h];
                }
                sm[EHS_OFF + g * 16 + h] = se;
                sm[ECS_OFF + g * 16 + h] = sc;
            }
        } else {
            // ========== GEMM-B group: warps 4-15, J=2 register tiling ==========
            // old-rows (m=1..19) partial for step t+1; 12 K-slices x 29 units
            const int u0lane = tid - 128;
            const int cB = u0lane >> 5;       // 0..11 (one warp per K-slice)
            const int jB = u0lane & 31;       // j and j+32
            const int u0 = cB * 29;
            int m0  = 1 + u0 / 18;
            int qq0 = u0 - (m0 - 1) * 18;
            int slot0 = (s + 19 + m0) % 20;
            int pos = slot0 * 18 + qq0;
            const uint4* wp = reinterpret_cast<const uint4*>(g_W1h) + (18 + u0) * 64 + jB;
            const ulonglong2* ringU = reinterpret_cast<const ulonglong2*>(sm);

            unsigned long long a00 = 0ull, a01 = 0ull, a02 = 0ull, a03 = 0ull;
            unsigned long long a10 = 0ull, a11 = 0ull, a12 = 0ull, a13 = 0ull;

            #pragma unroll 1
            for (int it = 0; it < 29; ++it) {
                uint4 wv0 = wp[0];
                uint4 wv1 = wp[32];
                wp += 64;
                unsigned long long w0a = h2f2(wv0.x), w0b = h2f2(wv0.y);
                unsigned long long w0c = h2f2(wv0.z), w0d = h2f2(wv0.w);
                unsigned long long w1a = h2f2(wv1.x), w1b = h2f2(wv1.y);
                unsigned long long w1c = h2f2(wv1.z), w1d = h2f2(wv1.w);
                int p2 = pos << 1;
                ulonglong2 rA, rB;
                rA = ringU[p2];        rB = ringU[p2 + 1];
                FMA2(a00, w0a, rA.x); FMA2(a00, w0b, rA.y); FMA2(a00, w0c, rB.x); FMA2(a00, w0d, rB.y);
                FMA2(a10, w1a, rA.x); FMA2(a10, w1b, rA.y); FMA2(a10, w1c, rB.x); FMA2(a10, w1d, rB.y);
                rA = ringU[720 + p2];  rB = ringU[720 + p2 + 1];
                FMA2(a01, w0a, rA.x); FMA2(a01, w0b, rA.y); FMA2(a01, w0c, rB.x); FMA2(a01, w0d, rB.y);
                FMA2(a11, w1a, rA.x); FMA2(a11, w1b, rA.y); FMA2(a11, w1c, rB.x); FMA2(a11, w1d, rB.y);
                rA = ringU[1440 + p2]; rB = ringU[1440 + p2 + 1];
                FMA2(a02, w0a, rA.x); FMA2(a02, w0b, rA.y); FMA2(a02, w0c, rB.x); FMA2(a02, w0d, rB.y);
                FMA2(a12, w1a, rA.x); FMA2(a12, w1b, rA.y); FMA2(a12, w1c, rB.x); FMA2(a12, w1d, rB.y);
                rA = ringU[2160 + p2]; rB = ringU[2160 + p2 + 1];
                FMA2(a03, w0a, rA.x); FMA2(a03, w0b, rA.y); FMA2(a03, w0c, rB.x); FMA2(a03, w0d, rB.y);
                FMA2(a13, w1a, rA.x); FMA2(a13, w1b, rA.y); FMA2(a13, w1c, rB.x); FMA2(a13, w1d, rB.y);
                ++pos; if (pos == 360) pos = 0;
            }
            float4* psb4 = reinterpret_cast<float4*>(&sm[PSB_OFF]);
            psb4[cB * 64 + jB] = make_float4(
                pair_sum(a00), pair_sum(a01), pair_sum(a02), pair_sum(a03));
            psb4[cB * 64 + jB + 32] = make_float4(
                pair_sum(a10), pair_sum(a11), pair_sum(a12), pair_sum(a13));
            asm volatile("bar.sync 2, 384;" ::: "memory");
            if (tid < 384) {
                int r = tid - 128, jr = r >> 2, gr = r & 3;
                float sacc = 0.0f;
                #pragma unroll
                for (int c = 0; c < 12; ++c)
                    sacc += sm[PSB_OFF + (c * 64 + jr) * 4 + gr];
                sm[OLDPS_OFF + ((t + 1) & 1) * 256 + jr * 4 + gr] = sacc;
            }
        }
        __syncthreads();

        head = s;
    }
}

extern "C" void kernel_launch(void* const* d_in, const int* in_sizes, int n_in,
                              void* d_out, int out_size) {
    const float* x      = (const float*)d_in[0];
    const float* pred0  = (const float*)d_in[1];
    const float* gate0  = (const float*)d_in[2];
    const float* W_ih   = (const float*)d_in[3];
    const float* W_hh   = (const float*)d_in[4];
    const float* b_ih   = (const float*)d_in[5];
    const float* b_hh   = (const float*)d_in[6];
    const float* W_o    = (const float*)d_in[7];
    const float* b_o    = (const float*)d_in[8];
    const float* W1     = (const float*)d_in[9];
    const float* b1     = (const float*)d_in[10];
    const float* W2     = (const float*)d_in[11];
    const float* b2     = (const float*)d_in[12];
    const float* Wg     = (const float*)d_in[13];
    const float* bg     = (const float*)d_in[14];
    const float* Wa_ih  = (const float*)d_in[15];
    const float* Wa_hh  = (const float*)d_in[16];
    const float* ba_ih  = (const float*)d_in[17];
    const float* ba_hh  = (const float*)d_in[18];
    float* out = (float*)d_out;

    cudaFuncSetAttribute(mmoe_main, cudaFuncAttributeMaxDynamicSharedMemorySize, SMEM_BYTES);

    build_w1h<<<(W1H_ELEMS + 255) / 256, 256>>>(W1);
    mmoe_main<<<NCTA, NTHREADS, SMEM_BYTES>>>(
        x, pred0, gate0, W_ih, W_hh, b_ih, b_hh, W_o, b_o,
        W1, b1, W2, b2, Wg, bg, Wa_ih, Wa_hh, ba_ih, ba_hh, out);
}

// round 6
// speedup vs baseline: 1.3374x; 1.3374x over previous
#include <cuda_runtime.h>
#include <cuda_fp16.h>
#include <math.h>

#define NSTEP 256
#define G 4
#define NCTA 128
#define NTHREADS 512

// fp16 W1, re-tiled: [unit(366)][j(64)][kkk(8)]; unit = m*18+qq for m=0..19,
// units 360..365 are zero padding (GEMM-B tail). k = qq*8+kkk, pad k>=129 -> 0
#define W1H_UNITS 366
#define W1H_ELEMS (W1H_UNITS*64*8)
__device__ __half g_W1h[W1H_ELEMS];

// ---- shared memory layout (float offsets) ----
// ring row = 144 floats; DOUBLE IMAGE: 40 slots per g (slot s and s+20 mirrored)
#define RING_OFF   0        // [4][40][144] = 23040
#define W1A_OFF    23040    // m=0 weights fp32 [33 q][64 j][4 kk] = 8448
#define WHH_OFF    31488    // [16 h'][8c*64gate] = 8192
#define WAIH_OFF   39680    // [2][16 k][64 gate] = 2048
#define WAHH_OFF   41728    // 2048
#define W2S_OFF    43776    // [16][65] = 1040
#define WIH_OFF    44816    // 512
#define BE_OFF     45328    // 512
#define PSB_OFF    45840    // GEMM-B partials [12 c][64 j][4 g] = 3072
#define OLDPS_OFF  48912    // [2 parity][64 j * 4 g] = 512
#define E1S_OFF    49424    // [4][64]
#define ZBUF_OFF   49680    // [4][64]
#define NC_OFF     49936    // [4][128]
#define B1S_OFF    50448    // 64
#define BAC_OFF    50512    // [2][64]
#define WGS_OFF    50640    // [8][16]
#define WOS_OFF    50768    // [8][16]
#define EHS_OFF    50896    // [4][16]
#define ECS_OFF    50960
#define AHS_OFF    51024    // [2][4][16]
#define ACS_OFF    51152
#define AIS_OFF    51280    // [4][16]
#define GSM_OFF    51344    // [4][8]
#define OSM_OFF    51376    // [4][8]
#define ERRH_OFF   51408    // [4][10]
#define B2S_OFF    51448
#define BGS_OFF    51464
#define BOS_OFF    51472
#define PRED_OFF   51480
#define THETA_OFF  51484
#define SMEM_FLOATS 51488
#define SMEM_BYTES  (SMEM_FLOATS * 4)

__device__ __forceinline__ float sigf(float v) {
    return __fdividef(1.0f, 1.0f + __expf(-v));
}

#define FMA2(acc, a, b) \
    asm("fma.rn.f32x2 %0, %1, %2, %0;" : "+l"(acc) : "l"(a), "l"(b))

__device__ __forceinline__ float pair_sum(unsigned long long v) {
    union { unsigned long long u; float2 f; } cv; cv.u = v;
    return cv.f.x + cv.f.y;
}

__device__ __forceinline__ unsigned long long h2f2(unsigned int h2) {
    union { float2 f; unsigned long long u; } cv;
    cv.f = __half22float2(*reinterpret_cast<const __half2*>(&h2));
    return cv.u;
}

__global__ void build_w1h(const float* __restrict__ W1) {
    int idx = blockIdx.x * 256 + threadIdx.x;
    if (idx >= W1H_ELEMS) return;
    int kkk = idx & 7;
    int f8  = idx >> 3;
    int j   = f8 & 63;
    int mu  = f8 >> 6;          // unit in [0,366)
    float v = 0.0f;
    if (mu < 360) {
        int m  = mu / 18;
        int qq = mu - m * 18;
        int k  = qq * 8 + kkk;
        if (k < 129) v = W1[j * 2580 + m * 129 + k];
    }
    g_W1h[idx] = __float2half(v);
}

__global__ __launch_bounds__(NTHREADS, 1)
void mmoe_main(
    const float* __restrict__ x,      const float* __restrict__ pred0,
    const float* __restrict__ gate0,
    const float* __restrict__ W_ih,   const float* __restrict__ W_hh,
    const float* __restrict__ b_ih,   const float* __restrict__ b_hh,
    const float* __restrict__ W_o,    const float* __restrict__ b_o,
    const float* __restrict__ W1,     const float* __restrict__ b1,
    const float* __restrict__ W2,     const float* __restrict__ b2,
    const float* __restrict__ Wg,     const float* __restrict__ bg,
    const float* __restrict__ Wa_ih,  const float* __restrict__ Wa_hh,
    const float* __restrict__ ba_ih,  const float* __restrict__ ba_hh,
    float* __restrict__ out)
{
    extern __shared__ float sm[];
    const int tid = threadIdx.x;
    const int b0  = blockIdx.x * G;

    // ---------- init shared ----------
    for (int i = tid; i < 23040; i += NTHREADS) {
        int pos = i % 144;
        sm[RING_OFF + i] = (pos == 128) ? 0.5f : 0.0f;
    }
    for (int i = tid; i < 8448; i += NTHREADS) {
        int kk = i & 3, jj = (i >> 2) & 63, q = i >> 8;
        int k = q * 4 + kk;
        sm[W1A_OFF + i] = (k < 129) ? W1[jj * 2580 + k] : 0.0f;
    }
    for (int i = tid; i < 8192; i += NTHREADS) {
        int h = i >> 9, cg = i & 511;
        sm[WHH_OFF + i] = W_hh[cg * 16 + h];
    }
    for (int i = tid; i < 2048; i += NTHREADS) {
        int l = i >> 10, r = i & 1023, k = r >> 6, gate = r & 63;
        sm[WAIH_OFF + i] = Wa_ih[l * 1024 + gate * 16 + k];
        sm[WAHH_OFF + i] = Wa_hh[l * 1024 + gate * 16 + k];
    }
    for (int i = tid; i < 1040; i += NTHREADS) {
        int j2 = i / 65, k = i - j2 * 65;
        sm[W2S_OFF + i] = (k < 64) ? W2[j2 * 64 + k] : 0.0f;
    }
    if (tid < 512) {
        sm[WIH_OFF + tid] = W_ih[tid];
        sm[BE_OFF + tid]  = b_ih[tid] + b_hh[tid];
    }
    if (tid < 256) {
        // initial old-rows partial: rows m=1..19 are (0,...,0, 0.5)
        int jj = tid >> 2, gg = tid & 3;
        float sacc = 0.0f;
        for (int m = 1; m < 20; ++m) sacc += W1[jj * 2580 + m * 129 + 128];
        sm[OLDPS_OFF + jj * 4 + gg] = 0.5f * sacc;
    }
    if (tid < 128) {
        sm[BAC_OFF + tid] = ba_ih[tid] + ba_hh[tid];
        sm[WGS_OFF + tid] = Wg[tid];
        sm[WOS_OFF + tid] = W_o[tid];
        sm[AHS_OFF + tid] = 0.0f;
        sm[ACS_OFF + tid] = 0.0f;
    }
    if (tid < 64) { sm[B1S_OFF + tid] = b1[tid]; sm[EHS_OFF + tid] = 0.0f; sm[ECS_OFF + tid] = 0.0f; }
    if (tid < 40) sm[ERRH_OFF + tid] = 0.5f;
    if (tid < 32) sm[GSM_OFF + tid] = gate0[b0 * 8 + tid];
    if (tid < 16) sm[B2S_OFF + tid] = b2[tid];
    if (tid < 8)  { sm[BGS_OFF + tid] = bg[tid]; sm[BOS_OFF + tid] = b_o[tid]; }
    if (tid < 4)  sm[PRED_OFF + tid] = pred0[b0 + tid];
    __syncthreads();

    int head = 0;

    for (int t = 0; t < NSTEP; ++t) {
        int s = head - 1; if (s < 0) s = 19;   // nh_slot

        // ---- phase 2: experts (all 512 threads); error + x folded in ----
        {
            int g = tid >> 7, c = (tid >> 4) & 7, h = tid & 15;
            int cg = c << 6;
            float xv = __ldg(&x[(b0 + g) * NSTEP + t]);
            float zi = sm[BE_OFF + cg + h]      + xv * sm[WIH_OFF + cg + h];
            float zf = sm[BE_OFF + cg + 16 + h] + xv * sm[WIH_OFF + cg + 16 + h];
            float zg = sm[BE_OFF + cg + 32 + h] + xv * sm[WIH_OFF + cg + 32 + h];
            float zo = sm[BE_OFF + cg + 48 + h] + xv * sm[WIH_OFF + cg + 48 + h];
            #pragma unroll
            for (int k = 0; k < 16; ++k) {
                float ev = sm[EHS_OFF + g * 16 + k];
                const float* wr = &sm[WHH_OFF + k * 512 + cg];
                zi += ev * wr[h];
                zf += ev * wr[16 + h];
                zg += ev * wr[32 + h];
                zo += ev * wr[48 + h];
            }
            float c2 = sigf(zf) * sm[ECS_OFF + g * 16 + h] + sigf(zi) * tanhf(zg);
            float hn = sigf(zo) * tanhf(c2);
            int rbase = (g * 40 + s) * 144 + c * 16 + h;
            sm[RING_OFF + rbase] = hn;
            sm[RING_OFF + rbase + 2880] = hn;       // mirror image (+20 slots)
            sm[NC_OFF + g * 128 + c * 16 + h] = c2;
        }
        if (tid < 4) {
            float xv = x[(b0 + tid) * NSTEP + t];
            float e = xv - sm[PRED_OFF + tid];
            sm[ERRH_OFF + tid * 10 + (t % 10)] = e;
            int rbase = (tid * 40 + s) * 144 + 128;
            sm[RING_OFF + rbase] = e;
            sm[RING_OFF + rbase + 2880] = e;
        }
        __syncthreads();

        if (tid < 128) {
            // ================= small group: warps 0-3 =================
            // ---- GEMM-A: new-row slice (m=0) + old partial -> e1 ----
            {
                int jA = tid & 63, gp = tid >> 6;
                const float4* wA = reinterpret_cast<const float4*>(&sm[W1A_OFF]);
                const float4* r4 = reinterpret_cast<const float4*>(sm);
                int rb0 = ((2 * gp)     * 40 + s) * 36;
                int rb1 = ((2 * gp + 1) * 40 + s) * 36;
                float acc0 = 0.0f, acc1 = 0.0f;
                #pragma unroll 3
                for (int q = 0; q < 33; ++q) {
                    float4 w  = wA[q * 64 + jA];
                    float4 v0 = r4[rb0 + q];
                    acc0 += w.x * v0.x + w.y * v0.y + w.z * v0.z + w.w * v0.w;
                    float4 v1 = r4[rb1 + q];
                    acc1 += w.x * v1.x + w.y * v1.y + w.z * v1.z + w.w * v1.w;
                }
                int par = (t & 1) * 256;
                float bb = sm[B1S_OFF + jA];
                sm[E1S_OFF + (2 * gp) * 64 + jA] =
                    fmaxf(acc0 + sm[OLDPS_OFF + par + jA * 4 + 2 * gp] + bb, 0.0f);
                sm[E1S_OFF + (2 * gp + 1) * 64 + jA] =
                    fmaxf(acc1 + sm[OLDPS_OFF + par + jA * 4 + 2 * gp + 1] + bb, 0.0f);
            }
            asm volatile("bar.sync 1, 128;" ::: "memory");

            // ---- phase 5: MLP2 | expert heads | theta ----
            if (tid < 64) {
                int g = tid >> 4, j2 = tid & 15;
                float sacc = sm[B2S_OFF + j2];
                #pragma unroll
                for (int k = 0; k < 64; ++k)
                    sacc += sm[E1S_OFF + g * 64 + k] * sm[W2S_OFF + j2 * 65 + k];
                sm[AIS_OFF + g * 16 + j2] = fmaxf(sacc, 0.0f);
            } else if (tid < 96) {
                int u = tid - 64, g = u >> 3, c = u & 7;
                float sacc = sm[BOS_OFF + c];
                const float* rr = &sm[RING_OFF + (g * 40 + s) * 144 + c * 16];
                #pragma unroll
                for (int h = 0; h < 16; ++h) sacc += rr[h] * sm[WOS_OFF + c * 16 + h];
                sm[OSM_OFF + g * 8 + c] = sacc;
            } else if (tid < 100) {
                int g = tid - 96;
                float sacc = 0.0f;
                #pragma unroll
                for (int i2 = 0; i2 < 10; ++i2) sacc += fabsf(sm[ERRH_OFF + g * 10 + i2]);
                sm[THETA_OFF + g] = fminf(0.25f * sacc, 1.0f);
            }
            asm volatile("bar.sync 1, 128;" ::: "memory");

            // ---- phase 6: agent, 2 stacked LSTM layers ----
            #pragma unroll 1
            for (int l = 0; l < 2; ++l) {
                #pragma unroll
                for (int r = 0; r < 2; ++r) {
                    int e = tid + (r << 7);
                    int g = e >> 6, gate = e & 63;
                    const float* inp = (l == 0) ? &sm[AIS_OFF + g * 16]
                                                : &sm[AHS_OFF + g * 16];
                    const float* hp  = &sm[AHS_OFF + l * 64 + g * 16];
                    float z = sm[BAC_OFF + l * 64 + gate];
                    const float* wi = &sm[WAIH_OFF + l * 1024 + gate];
                    const float* wh = &sm[WAHH_OFF + l * 1024 + gate];
                    #pragma unroll
                    for (int k = 0; k < 16; ++k)
                        z += inp[k] * wi[k * 64] + hp[k] * wh[k * 64];
                    sm[ZBUF_OFF + g * 64 + gate] = z;
                }
                asm volatile("bar.sync 1, 128;" ::: "memory");
                if (tid < 64) {
                    int g2 = tid >> 4, h = tid & 15;
                    float zi = sm[ZBUF_OFF + g2 * 64 + h];
                    float zf = sm[ZBUF_OFF + g2 * 64 + 16 + h];
                    float zg = sm[ZBUF_OFF + g2 * 64 + 32 + h];
                    float zo = sm[ZBUF_OFF + g2 * 64 + 48 + h];
                    float c2 = sigf(zf) * sm[ACS_OFF + l * 64 + g2 * 16 + h]
                             + sigf(zi) * tanhf(zg);
                    float hn = sigf(zo) * tanhf(c2);
                    sm[ACS_OFF + l * 64 + g2 * 16 + h] = c2;
                    sm[AHS_OFF + l * 64 + g2 * 16 + h] = hn;
                }
                asm volatile("bar.sync 1, 128;" ::: "memory");
            }

            // ---- phase 7a: gate logits ----
            if (tid < 32) {
                int g = tid >> 3, c = tid & 7;
                float sacc = sm[BGS_OFF + c];
                const float* a1p = &sm[AHS_OFF + 64 + g * 16];
                #pragma unroll
                for (int k = 0; k < 16; ++k) sacc += a1p[k] * sm[WGS_OFF + c * 16 + k];
                sm[ZBUF_OFF + g * 8 + c] = sacc;
            }
            asm volatile("bar.sync 1, 128;" ::: "memory");

            // ---- phase 7b: softmax + blend + pred ----
            if (tid < 4) {
                int g = tid;
                float mx = -1e30f;
                #pragma unroll
                for (int c = 0; c < 8; ++c) mx = fmaxf(mx, sm[ZBUF_OFF + g * 8 + c]);
                float ex[8], ssum = 0.0f;
                #pragma unroll
                for (int c = 0; c < 8; ++c) { ex[c] = __expf(sm[ZBUF_OFF + g * 8 + c] - mx); ssum += ex[c]; }
                float inv = __fdividef(1.0f, ssum);
                float th = sm[THETA_OFF + g];
                float pred = 0.0f;
                #pragma unroll
                for (int c = 0; c < 8; ++c) {
                    float gf = ex[c] * inv * th + sm[GSM_OFF + g * 8 + c] * (1.0f - th);
                    sm[GSM_OFF + g * 8 + c] = gf;
                    pred += gf * sm[OSM_OFF + g * 8 + c];
                }
                sm[PRED_OFF + g] = pred;
                out[(b0 + g) * NSTEP + t] = pred;
            }
            asm volatile("bar.sync 1, 128;" ::: "memory");

            // ---- phase 7c: eh2 / ec2 ----
            if (tid < 64) {
                int g = tid >> 4, h = tid & 15;
                const float* rr = &sm[RING_OFF + (g * 40 + s) * 144];
                const float* nc = &sm[NC_OFF + g * 128];
                float se = 0.0f, sc = 0.0f;
                #pragma unroll
                for (int c = 0; c < 8; ++c) {
                    float gf = sm[GSM_OFF + g * 8 + c];
                    se += gf * rr[c * 16 + h];
                    sc += gf * nc[c * 16 + h];
                }
                sm[EHS_OFF + g * 16 + h] = se;
                sm[ECS_OFF + g * 16 + h] = sc;
            }
        } else {
            // ========== GEMM-B: warps 4-15, J=2 tiling, AFFINE fully-unrolled ==========
            // old-rows (m=1..19) partial for step t+1; 12 K-slices x 29 units
            const int u0lane = tid - 128;
            const int cB = u0lane >> 5;       // 0..11 (one warp per K-slice)
            const int jB = u0lane & 31;       // j and j+32
            const int u0 = cB * 29;
            int m0  = 1 + u0 / 18;
            int qq0 = u0 - (m0 - 1) * 18;
            int slot0 = (s + 19 + m0) % 20;   // in [0,20); reads extend into mirror
            const int pos0 = slot0 * 18 + qq0;
            const uint4* __restrict__ wp =
                reinterpret_cast<const uint4*>(g_W1h) + (18 + u0) * 64 + jB;
            const ulonglong2* __restrict__ ringU =
                reinterpret_cast<const ulonglong2*>(sm);

            unsigned long long a00 = 0ull, a01 = 0ull, a02 = 0ull, a03 = 0ull;
            unsigned long long a10 = 0ull, a11 = 0ull, a12 = 0ull, a13 = 0ull;

            #pragma unroll
            for (int it = 0; it < 29; ++it) {
                uint4 wv0 = wp[it * 64];
                uint4 wv1 = wp[it * 64 + 32];
                unsigned long long w0a = h2f2(wv0.x), w0b = h2f2(wv0.y);
                unsigned long long w0c = h2f2(wv0.z), w0d = h2f2(wv0.w);
                unsigned long long w1a = h2f2(wv1.x), w1b = h2f2(wv1.y);
                unsigned long long w1c = h2f2(wv1.z), w1d = h2f2(wv1.w);
                int p2 = (pos0 + it) << 1;
                ulonglong2 rA, rB;
                rA = ringU[p2];        rB = ringU[p2 + 1];
                FMA2(a00, w0a, rA.x); FMA2(a00, w0b, rA.y); FMA2(a00, w0c, rB.x); FMA2(a00, w0d, rB.y);
                FMA2(a10, w1a, rA.x); FMA2(a10, w1b, rA.y); FMA2(a10, w1c, rB.x); FMA2(a10, w1d, rB.y);
                rA = ringU[1440 + p2]; rB = ringU[1440 + p2 + 1];
                FMA2(a01, w0a, rA.x); FMA2(a01, w0b, rA.y); FMA2(a01, w0c, rB.x); FMA2(a01, w0d, rB.y);
                FMA2(a11, w1a, rA.x); FMA2(a11, w1b, rA.y); FMA2(a11, w1c, rB.x); FMA2(a11, w1d, rB.y);
                rA = ringU[2880 + p2]; rB = ringU[2880 + p2 + 1];
                FMA2(a02, w0a, rA.x); FMA2(a02, w0b, rA.y); FMA2(a02, w0c, rB.x); FMA2(a02, w0d, rB.y);
                FMA2(a12, w1a, rA.x); FMA2(a12, w1b, rA.y); FMA2(a12, w1c, rB.x); FMA2(a12, w1d, rB.y);
                rA = ringU[4320 + p2]; rB = ringU[4320 + p2 + 1];
                FMA2(a03, w0a, rA.x); FMA2(a03, w0b, rA.y); FMA2(a03, w0c, rB.x); FMA2(a03, w0d, rB.y);
                FMA2(a13, w1a, rA.x); FMA2(a13, w1b, rA.y); FMA2(a13, w1c, rB.x); FMA2(a13, w1d, rB.y);
            }
            float4* psb4 = reinterpret_cast<float4*>(&sm[PSB_OFF]);
            psb4[cB * 64 + jB] = make_float4(
                pair_sum(a00), pair_sum(a01), pair_sum(a02), pair_sum(a03));
            psb4[cB * 64 + jB + 32] = make_float4(
                pair_sum(a10), pair_sum(a11), pair_sum(a12), pair_sum(a13));
            asm volatile("bar.sync 2, 384;" ::: "memory");
            if (tid < 384) {
                int r = tid - 128, jr = r >> 2, gr = r & 3;
                float sacc = 0.0f;
                #pragma unroll
                for (int c = 0; c < 12; ++c)
                    sacc += sm[PSB_OFF + (c * 64 + jr) * 4 + gr];
                sm[OLDPS_OFF + ((t + 1) & 1) * 256 + jr * 4 + gr] = sacc;
            }
        }
        __syncthreads();

        head = s;
    }
}

extern "C" void kernel_launch(void* const* d_in, const int* in_sizes, int n_in,
                              void* d_out, int out_size) {
    const float* x      = (const float*)d_in[0];
    const float* pred0  = (const float*)d_in[1];
    const float* gate0  = (const float*)d_in[2];
    const float* W_ih   = (const float*)d_in[3];
    const float* W_hh   = (const float*)d_in[4];
    const float* b_ih   = (const float*)d_in[5];
    const float* b_hh   = (const float*)d_in[6];
    const float* W_o    = (const float*)d_in[7];
    const float* b_o    = (const float*)d_in[8];
    const float* W1     = (const float*)d_in[9];
    const float* b1     = (const float*)d_in[10];
    const float* W2     = (const float*)d_in[11];
    const float* b2     = (const float*)d_in[12];
    const float* Wg     = (const float*)d_in[13];
    const float* bg     = (const float*)d_in[14];
    const float* Wa_ih  = (const float*)d_in[15];
    const float* Wa_hh  = (const float*)d_in[16];
    const float* ba_ih  = (const float*)d_in[17];
    const float* ba_hh  = (const float*)d_in[18];
    float* out = (float*)d_out;

    cudaFuncSetAttribute(mmoe_main, cudaFuncAttributeMaxDynamicSharedMemorySize, SMEM_BYTES);

    build_w1h<<<(W1H_ELEMS + 255) / 256, 256>>>(W1);
    mmoe_main<<<NCTA, NTHREADS, SMEM_BYTES>>>(
        x, pred0, gate0, W_ih, W_hh, b_ih, b_hh, W_o, b_o,
        W1, b1, W2, b2, Wg, bg, Wa_ih, Wa_hh, ba_ih, ba_hh, out);
}

// round 7
// speedup vs baseline: 1.8088x; 1.3524x over previous
#include <cuda_runtime.h>
#include <cuda_fp16.h>
#include <math.h>

#define NSTEP 256
#define G 4
#define NCTA 128
#define NTHREADS 512

// A-fragment-packed fp16 W1 for mma.m16n8k16:
// jobs: 0..170 real = (m-1)*9+kb for m=1..19, kb=0..8; 171..179 zero pad.
// layout: [job(180)][jtile(4)][lane(32)] -> uint4 (8 halves in fragment order)
#define W1F_JOBS 180
#define W1F_U4   (W1F_JOBS * 4 * 32)
__device__ uint4 g_W1f[W1F_U4];

// ---- shared memory layout (float offsets) ----
// fp32 ring row = 144 floats: [0..127]=nh, [128]=error, [129..143]=0 (20 slots)
#define RING_OFF   0        // [4][20][144] = 11520
#define RH_OFF     11520    // fp16 B-fragment ring [20][9][32][4] halves = 11520 floats
#define W1A_OFF    23040    // m=0 weights fp32 [33 q][64 j][4 kk] = 8448
#define WHH_OFF    31488    // [16 h'][8c*64gate] = 8192
#define WAIH_OFF   39680    // [2][16 k][64 gate] = 2048
#define WAHH_OFF   41728    // 2048
#define W2S_OFF    43776    // [16][65] = 1040
#define WIH_OFF    44816    // 512
#define BE_OFF     45328    // 512
#define PSB_OFF    45840    // GEMM-B partials [12 w][64 j][4 g] = 3072
#define OLDPS_OFF  48912    // [2 parity][64 j * 4 g] = 512
#define E1S_OFF    49424    // [4][64]
#define ZBUF_OFF   49680    // [4][64]
#define NC_OFF     49936    // [4][128]
#define B1S_OFF    50448    // 64
#define BAC_OFF    50512    // [2][64]
#define WGS_OFF    50640    // [8][16]
#define WOS_OFF    50768    // [8][16]
#define EHS_OFF    50896    // [4][16]
#define ECS_OFF    50960
#define AHS_OFF    51024    // [2][4][16]
#define ACS_OFF    51152
#define AIS_OFF    51280    // [4][16]
#define GSM_OFF    51344    // [4][8]
#define OSM_OFF    51376    // [4][8]
#define ERRH_OFF   51408    // [4][10]
#define B2S_OFF    51448
#define BGS_OFF    51464
#define BOS_OFF    51472
#define PRED_OFF   51480
#define THETA_OFF  51484
#define SMEM_FLOATS 51488
#define SMEM_BYTES  (SMEM_FLOATS * 4)

__device__ __forceinline__ float sigf(float v) {
    return __fdividef(1.0f, 1.0f + __expf(-v));
}

// Build fragment-ordered fp16 weights for mma.m16n8k16 (A, row-major 16x16 tiles)
__global__ void build_w1f(const float* __restrict__ W1) {
    int idx = blockIdx.x * 256 + threadIdx.x;
    if (idx >= W1F_U4) return;
    int lane = idx & 31;
    int jt   = (idx >> 5) & 3;
    int job  = idx >> 7;
    int r  = lane >> 2;
    int tg = lane & 3;
    float f[8];
    #pragma unroll
    for (int i = 0; i < 8; ++i) f[i] = 0.0f;
    if (job < 171) {
        int m  = 1 + job / 9;
        int kb = job - (m - 1) * 9;
        int j0 = jt * 16;
        int kbase = kb * 16;
        // fragment order: a0,a1 (row r, cols 2tg,2tg+1); a2,a3 (row r+8, same);
        //                 a4,a5 (row r, cols 2tg+8,2tg+9); a6,a7 (row r+8, same)
        const int dj[8] = {r, r, r + 8, r + 8, r, r, r + 8, r + 8};
        const int dc[8] = {2*tg, 2*tg+1, 2*tg, 2*tg+1, 2*tg+8, 2*tg+9, 2*tg+8, 2*tg+9};
        #pragma unroll
        for (int i = 0; i < 8; ++i) {
            int kc = kbase + dc[i];
            if (kc < 129) f[i] = W1[(j0 + dj[i]) * 2580 + m * 129 + kc];
        }
    }
    __half h[8];
    #pragma unroll
    for (int i = 0; i < 8; ++i) h[i] = __float2half(f[i]);
    uint4 u;
    u.x = *reinterpret_cast<unsigned int*>(&h[0]);
    u.y = *reinterpret_cast<unsigned int*>(&h[2]);
    u.z = *reinterpret_cast<unsigned int*>(&h[4]);
    u.w = *reinterpret_cast<unsigned int*>(&h[6]);
    g_W1f[idx] = u;
}

__global__ __launch_bounds__(NTHREADS, 1)
void mmoe_main(
    const float* __restrict__ x,      const float* __restrict__ pred0,
    const float* __restrict__ gate0,
    const float* __restrict__ W_ih,   const float* __restrict__ W_hh,
    const float* __restrict__ b_ih,   const float* __restrict__ b_hh,
    const float* __restrict__ W_o,    const float* __restrict__ b_o,
    const float* __restrict__ W1,     const float* __restrict__ b1,
    const float* __restrict__ W2,     const float* __restrict__ b2,
    const float* __restrict__ Wg,     const float* __restrict__ bg,
    const float* __restrict__ Wa_ih,  const float* __restrict__ Wa_hh,
    const float* __restrict__ ba_ih,  const float* __restrict__ ba_hh,
    float* __restrict__ out)
{
    extern __shared__ float sm[];
    __half* rh = reinterpret_cast<__half*>(&sm[RH_OFF]);
    const int tid = threadIdx.x;
    const int b0  = blockIdx.x * G;

    // ---------- init shared ----------
    for (int i = tid; i < 11520; i += NTHREADS) {
        int pos = i % 144;
        sm[RING_OFF + i] = (pos == 128) ? 0.5f : 0.0f;
    }
    // fp16 fragment ring: zeros except the k=128 (error col, init 0.5) entries
    for (int i = tid; i < 23040; i += NTHREADS) {
        int q = i & 3, ln = (i >> 2) & 31, kb = (i >> 7) % 9;
        bool is05 = (q == 0) && ((ln & 3) == 0) && (ln < 16) && (kb == 8);
        rh[i] = __float2half(is05 ? 0.5f : 0.0f);
    }
    for (int i = tid; i < 8448; i += NTHREADS) {
        int kk = i & 3, jj = (i >> 2) & 63, q = i >> 8;
        int k = q * 4 + kk;
        sm[W1A_OFF + i] = (k < 129) ? W1[jj * 2580 + k] : 0.0f;
    }
    for (int i = tid; i < 8192; i += NTHREADS) {
        int h = i >> 9, cg = i & 511;
        sm[WHH_OFF + i] = W_hh[cg * 16 + h];
    }
    for (int i = tid; i < 2048; i += NTHREADS) {
        int l = i >> 10, r = i & 1023, k = r >> 6, gate = r & 63;
        sm[WAIH_OFF + i] = Wa_ih[l * 1024 + gate * 16 + k];
        sm[WAHH_OFF + i] = Wa_hh[l * 1024 + gate * 16 + k];
    }
    for (int i = tid; i < 1040; i += NTHREADS) {
        int j2 = i / 65, k = i - j2 * 65;
        sm[W2S_OFF + i] = (k < 64) ? W2[j2 * 64 + k] : 0.0f;
    }
    if (tid < 512) {
        sm[WIH_OFF + tid] = W_ih[tid];
        sm[BE_OFF + tid]  = b_ih[tid] + b_hh[tid];
    }
    if (tid < 256) {
        // initial old-rows partial: rows m=1..19 are (0,...,0, 0.5)
        int jj = tid >> 2, gg = tid & 3;
        float sacc = 0.0f;
        for (int m = 1; m < 20; ++m) sacc += W1[jj * 2580 + m * 129 + 128];
        sm[OLDPS_OFF + jj * 4 + gg] = 0.5f * sacc;
    }
    if (tid < 128) {
        sm[BAC_OFF + tid] = ba_ih[tid] + ba_hh[tid];
        sm[WGS_OFF + tid] = Wg[tid];
        sm[WOS_OFF + tid] = W_o[tid];
        sm[AHS_OFF + tid] = 0.0f;
        sm[ACS_OFF + tid] = 0.0f;
    }
    if (tid < 64) { sm[B1S_OFF + tid] = b1[tid]; sm[EHS_OFF + tid] = 0.0f; sm[ECS_OFF + tid] = 0.0f; }
    if (tid < 40) sm[ERRH_OFF + tid] = 0.5f;
    if (tid < 32) sm[GSM_OFF + tid] = gate0[b0 * 8 + tid];
    if (tid < 16) sm[B2S_OFF + tid] = b2[tid];
    if (tid < 8)  { sm[BGS_OFF + tid] = bg[tid]; sm[BOS_OFF + tid] = b_o[tid]; }
    if (tid < 4)  sm[PRED_OFF + tid] = pred0[b0 + tid];
    __syncthreads();

    int head = 0;

    for (int t = 0; t < NSTEP; ++t) {
        int s = head - 1; if (s < 0) s = 19;   // nh_slot

        // ---- phase 2: experts (all 512 threads); error + x folded in ----
        {
            int g = tid >> 7, c = (tid >> 4) & 7, h = tid & 15;
            int cg = c << 6;
            float xv = __ldg(&x[(b0 + g) * NSTEP + t]);
            float zi = sm[BE_OFF + cg + h]      + xv * sm[WIH_OFF + cg + h];
            float zf = sm[BE_OFF + cg + 16 + h] + xv * sm[WIH_OFF + cg + 16 + h];
            float zg = sm[BE_OFF + cg + 32 + h] + xv * sm[WIH_OFF + cg + 32 + h];
            float zo = sm[BE_OFF + cg + 48 + h] + xv * sm[WIH_OFF + cg + 48 + h];
            #pragma unroll
            for (int k = 0; k < 16; ++k) {
                float ev = sm[EHS_OFF + g * 16 + k];
                const float* wr = &sm[WHH_OFF + k * 512 + cg];
                zi += ev * wr[h];
                zf += ev * wr[16 + h];
                zg += ev * wr[32 + h];
                zo += ev * wr[48 + h];
            }
            float c2 = sigf(zf) * sm[ECS_OFF + g * 16 + h] + sigf(zi) * tanhf(zg);
            float hn = sigf(zo) * tanhf(c2);
            sm[RING_OFF + (g * 20 + s) * 144 + c * 16 + h] = hn;
            sm[NC_OFF + g * 128 + c * 16 + h] = c2;
            // fp16 B-fragment image: kblock = c, k-row-in-block = h
            int lane = (g << 2) | ((h & 7) >> 1);
            int q = (h & 1) | ((h >> 3) << 1);
            rh[((s * 9 + c) * 32 + lane) * 4 + q] = __float2half(hn);
        }
        if (tid < 4) {
            float xv = x[(b0 + tid) * NSTEP + t];
            float e = xv - sm[PRED_OFF + tid];
            sm[ERRH_OFF + tid * 10 + (t % 10)] = e;
            sm[RING_OFF + (tid * 20 + s) * 144 + 128] = e;
            rh[((s * 9 + 8) * 32 + (tid << 2)) * 4] = __float2half(e);
        }
        __syncthreads();

        if (tid < 128) {
            // ================= small group: warps 0-3 =================
            // ---- GEMM-A: new-row slice (m=0) + old partial -> e1 ----
            {
                int jA = tid & 63, gp = tid >> 6;
                const float4* wA = reinterpret_cast<const float4*>(&sm[W1A_OFF]);
                const float4* r4 = reinterpret_cast<const float4*>(sm);
                int rb0 = ((2 * gp)     * 20 + s) * 36;
                int rb1 = ((2 * gp + 1) * 20 + s) * 36;
                float acc0 = 0.0f, acc1 = 0.0f;
                #pragma unroll 3
                for (int q = 0; q < 33; ++q) {
                    float4 w  = wA[q * 64 + jA];
                    float4 v0 = r4[rb0 + q];
                    acc0 += w.x * v0.x + w.y * v0.y + w.z * v0.z + w.w * v0.w;
                    float4 v1 = r4[rb1 + q];
                    acc1 += w.x * v1.x + w.y * v1.y + w.z * v1.z + w.w * v1.w;
                }
                int par = (t & 1) * 256;
                float bb = sm[B1S_OFF + jA];
                sm[E1S_OFF + (2 * gp) * 64 + jA] =
                    fmaxf(acc0 + sm[OLDPS_OFF + par + jA * 4 + 2 * gp] + bb, 0.0f);
                sm[E1S_OFF + (2 * gp + 1) * 64 + jA] =
                    fmaxf(acc1 + sm[OLDPS_OFF + par + jA * 4 + 2 * gp + 1] + bb, 0.0f);
            }
            asm volatile("bar.sync 1, 128;" ::: "memory");

            // ---- phase 5: MLP2 | expert heads | theta ----
            if (tid < 64) {
                int g = tid >> 4, j2 = tid & 15;
                float sacc = sm[B2S_OFF + j2];
                #pragma unroll
                for (int k = 0; k < 64; ++k)
                    sacc += sm[E1S_OFF + g * 64 + k] * sm[W2S_OFF + j2 * 65 + k];
                sm[AIS_OFF + g * 16 + j2] = fmaxf(sacc, 0.0f);
            } else if (tid < 96) {
                int u = tid - 64, g = u >> 3, c = u & 7;
                float sacc = sm[BOS_OFF + c];
                const float* rr = &sm[RING_OFF + (g * 20 + s) * 144 + c * 16];
                #pragma unroll
                for (int h = 0; h < 16; ++h) sacc += rr[h] * sm[WOS_OFF + c * 16 + h];
                sm[OSM_OFF + g * 8 + c] = sacc;
            } else if (tid < 100) {
                int g = tid - 96;
                float sacc = 0.0f;
                #pragma unroll
                for (int i2 = 0; i2 < 10; ++i2) sacc += fabsf(sm[ERRH_OFF + g * 10 + i2]);
                sm[THETA_OFF + g] = fminf(0.25f * sacc, 1.0f);
            }
            asm volatile("bar.sync 1, 128;" ::: "memory");

            // ---- phase 6: agent, 2 stacked LSTM layers ----
            #pragma unroll 1
            for (int l = 0; l < 2; ++l) {
                #pragma unroll
                for (int r = 0; r < 2; ++r) {
                    int e = tid + (r << 7);
                    int g = e >> 6, gate = e & 63;
                    const float* inp = (l == 0) ? &sm[AIS_OFF + g * 16]
                                                : &sm[AHS_OFF + g * 16];
                    const float* hp  = &sm[AHS_OFF + l * 64 + g * 16];
                    float z = sm[BAC_OFF + l * 64 + gate];
                    const float* wi = &sm[WAIH_OFF + l * 1024 + gate];
                    const float* wh = &sm[WAHH_OFF + l * 1024 + gate];
                    #pragma unroll
                    for (int k = 0; k < 16; ++k)
                        z += inp[k] * wi[k * 64] + hp[k] * wh[k * 64];
                    sm[ZBUF_OFF + g * 64 + gate] = z;
                }
                asm volatile("bar.sync 1, 128;" ::: "memory");
                if (tid < 64) {
                    int g2 = tid >> 4, h = tid & 15;
                    float zi = sm[ZBUF_OFF + g2 * 64 + h];
                    float zf = sm[ZBUF_OFF + g2 * 64 + 16 + h];
                    float zg = sm[ZBUF_OFF + g2 * 64 + 32 + h];
                    float zo = sm[ZBUF_OFF + g2 * 64 + 48 + h];
                    float c2 = sigf(zf) * sm[ACS_OFF + l * 64 + g2 * 16 + h]
                             + sigf(zi) * tanhf(zg);
                    float hn = sigf(zo) * tanhf(c2);
                    sm[ACS_OFF + l * 64 + g2 * 16 + h] = c2;
                    sm[AHS_OFF + l * 64 + g2 * 16 + h] = hn;
                }
                asm volatile("bar.sync 1, 128;" ::: "memory");
            }

            // ---- phase 7a: gate logits ----
            if (tid < 32) {
                int g = tid >> 3, c = tid & 7;
                float sacc = sm[BGS_OFF + c];
                const float* a1p = &sm[AHS_OFF + 64 + g * 16];
                #pragma unroll
                for (int k = 0; k < 16; ++k) sacc += a1p[k] * sm[WGS_OFF + c * 16 + k];
                sm[ZBUF_OFF + g * 8 + c] = sacc;
            }
            asm volatile("bar.sync 1, 128;" ::: "memory");

            // ---- phase 7b: softmax + blend + pred ----
            if (tid < 4) {
                int g = tid;
                float mx = -1e30f;
                #pragma unroll
                for (int c = 0; c < 8; ++c) mx = fmaxf(mx, sm[ZBUF_OFF + g * 8 + c]);
                float ex[8], ssum = 0.0f;
                #pragma unroll
                for (int c = 0; c < 8; ++c) { ex[c] = __expf(sm[ZBUF_OFF + g * 8 + c] - mx); ssum += ex[c]; }
                float inv = __fdividef(1.0f, ssum);
                float th = sm[THETA_OFF + g];
                float pred = 0.0f;
                #pragma unroll
                for (int c = 0; c < 8; ++c) {
                    float gf = ex[c] * inv * th + sm[GSM_OFF + g * 8 + c] * (1.0f - th);
                    sm[GSM_OFF + g * 8 + c] = gf;
                    pred += gf * sm[OSM_OFF + g * 8 + c];
                }
                sm[PRED_OFF + g] = pred;
                out[(b0 + g) * NSTEP + t] = pred;
            }
            asm volatile("bar.sync 1, 128;" ::: "memory");

            // ---- phase 7c: eh2 / ec2 ----
            if (tid < 64) {
                int g = tid >> 4, h = tid & 15;
                const float* rr = &sm[RING_OFF + (g * 20 + s) * 144];
                const float* nc = &sm[NC_OFF + g * 128];
                float se = 0.0f, sc = 0.0f;
                #pragma unroll
                for (int c = 0; c < 8; ++c) {
                    float gf = sm[GSM_OFF + g * 8 + c];
                    se += gf * rr[c * 16 + h];
                    sc += gf * nc[c * 16 + h];
                }
                sm[EHS_OFF + g * 16 + h] = se;
                sm[ECS_OFF + g * 16 + h] = sc;
            }
        } else {
            // ========== GEMM-B: warps 4-15, tensor cores (mma.m16n8k16) ==========
            // old-rows (m=1..19) partial for step t+1. 180 (row,kblock) jobs,
            // 15 per warp; jobs >= 171 have zero weights (ring read is harmless).
            const int w    = (tid >> 5) - 4;   // 0..11
            const int lane = tid & 31;
            int jb0 = w * 15;
            int m   = 1 + jb0 / 9;
            int kb  = jb0 - (m - 1) * 9;

            float d0[4], d1[4], d2[4], d3[4];
            #pragma unroll
            for (int i = 0; i < 4; ++i) { d0[i]=0.f; d1[i]=0.f; d2[i]=0.f; d3[i]=0.f; }

            const uint4* __restrict__ wA = g_W1f + (jb0 * 4) * 32 + lane;
            const unsigned int* __restrict__ rhU =
                reinterpret_cast<const unsigned int*>(rh);

            #pragma unroll
            for (int it = 0; it < 15; ++it) {
                int slot = s + m - 1; if (slot >= 20) slot -= 20;
                int bofs = ((slot * 9 + kb) * 32 + lane) * 2;  // in b32 units
                unsigned int bx = rhU[bofs];
                unsigned int by = rhU[bofs + 1];
                uint4 a0 = wA[it * 128];
                uint4 a1 = wA[it * 128 + 32];
                uint4 a2 = wA[it * 128 + 64];
                uint4 a3 = wA[it * 128 + 96];
                asm volatile("mma.sync.aligned.m16n8k16.row.col.f32.f16.f16.f32 "
                    "{%0,%1,%2,%3}, {%4,%5,%6,%7}, {%8,%9}, {%0,%1,%2,%3};"
                    : "+f"(d0[0]), "+f"(d0[1]), "+f"(d0[2]), "+f"(d0[3])
                    : "r"(a0.x), "r"(a0.y), "r"(a0.z), "r"(a0.w), "r"(bx), "r"(by));
                asm volatile("mma.sync.aligned.m16n8k16.row.col.f32.f16.f16.f32 "
                    "{%0,%1,%2,%3}, {%4,%5,%6,%7}, {%8,%9}, {%0,%1,%2,%3};"
                    : "+f"(d1[0]), "+f"(d1[1]), "+f"(d1[2]), "+f"(d1[3])
                    : "r"(a1.x), "r"(a1.y), "r"(a1.z), "r"(a1.w), "r"(bx), "r"(by));
                asm volatile("mma.sync.aligned.m16n8k16.row.col.f32.f16.f16.f32 "
                    "{%0,%1,%2,%3}, {%4,%5,%6,%7}, {%8,%9}, {%0,%1,%2,%3};"
                    : "+f"(d2[0]), "+f"(d2[1]), "+f"(d2[2]), "+f"(d2[3])
                    : "r"(a2.x), "r"(a2.y), "r"(a2.z), "r"(a2.w), "r"(bx), "r"(by));
                asm volatile("mma.sync.aligned.m16n8k16.row.col.f32.f16.f16.f32 "
                    "{%0,%1,%2,%3}, {%4,%5,%6,%7}, {%8,%9}, {%0,%1,%2,%3};"
                    : "+f"(d3[0]), "+f"(d3[1]), "+f"(d3[2]), "+f"(d3[3])
                    : "r"(a3.x), "r"(a3.y), "r"(a3.z), "r"(a3.w), "r"(bx), "r"(by));
                ++kb; if (kb == 9) { kb = 0; ++m; }
            }
            // epilogue: lanes with tg<2 hold the real g columns (n = 2tg+{0,1})
            {
                int tg = lane & 3, gr = lane >> 2;
                if (tg < 2) {
                    float* pb = &sm[PSB_OFF + (w * 64) * 4 + 2 * tg];
                    pb[(gr     ) * 4] = d0[0]; pb[(gr     ) * 4 + 1] = d0[1];
                    pb[(gr +  8) * 4] = d0[2]; pb[(gr +  8) * 4 + 1] = d0[3];
                    pb[(gr + 16) * 4] = d1[0]; pb[(gr + 16) * 4 + 1] = d1[1];
                    pb[(gr + 24) * 4] = d1[2]; pb[(gr + 24) * 4 + 1] = d1[3];
                    pb[(gr + 32) * 4] = d2[0]; pb[(gr + 32) * 4 + 1] = d2[1];
                    pb[(gr + 40) * 4] = d2[2]; pb[(gr + 40) * 4 + 1] = d2[3];
                    pb[(gr + 48) * 4] = d3[0]; pb[(gr + 48) * 4 + 1] = d3[1];
                    pb[(gr + 56) * 4] = d3[2]; pb[(gr + 56) * 4 + 1] = d3[3];
                }
            }
            asm volatile("bar.sync 2, 384;" ::: "memory");
            if (tid < 384) {
                int r = tid - 128, jr = r >> 2, gr = r & 3;
                float sacc = 0.0f;
                #pragma unroll
                for (int c = 0; c < 12; ++c)
                    sacc += sm[PSB_OFF + (c * 64 + jr) * 4 + gr];
                sm[OLDPS_OFF + ((t + 1) & 1) * 256 + jr * 4 + gr] = sacc;
            }
        }
        __syncthreads();

        head = s;
    }
}

extern "C" void kernel_launch(void* const* d_in, const int* in_sizes, int n_in,
                              void* d_out, int out_size) {
    const float* x      = (const float*)d_in[0];
    const float* pred0  = (const float*)d_in[1];
    const float* gate0  = (const float*)d_in[2];
    const float* W_ih   = (const float*)d_in[3];
    const float* W_hh   = (const float*)d_in[4];
    const float* b_ih   = (const float*)d_in[5];
    const float* b_hh   = (const float*)d_in[6];
    const float* W_o    = (const float*)d_in[7];
    const float* b_o    = (const float*)d_in[8];
    const float* W1     = (const float*)d_in[9];
    const float* b1     = (const float*)d_in[10];
    const float* W2     = (const float*)d_in[11];
    const float* b2     = (const float*)d_in[12];
    const float* Wg     = (const float*)d_in[13];
    const float* bg     = (const float*)d_in[14];
    const float* Wa_ih  = (const float*)d_in[15];
    const float* Wa_hh  = (const float*)d_in[16];
    const float* ba_ih  = (const float*)d_in[17];
    const float* ba_hh  = (const float*)d_in[18];
    float* out = (float*)d_out;

    cudaFuncSetAttribute(mmoe_main, cudaFuncAttributeMaxDynamicSharedMemorySize, SMEM_BYTES);

    build_w1f<<<(W1F_U4 + 255) / 256, 256>>>(W1);
    mmoe_main<<<NCTA, NTHREADS, SMEM_BYTES>>>(
        x, pred0, gate0, W_ih, W_hh, b_ih, b_hh, W_o, b_o,
        W1, b1, W2, b2, Wg, bg, Wa_ih, Wa_hh, ba_ih, ba_hh, out);
}

// round 8
// speedup vs baseline: 2.1767x; 1.2034x over previous
#include <cuda_runtime.h>
#include <cuda_fp16.h>
#include <math.h>

#define NSTEP 256
#define G 4
#define NCTA 128
#define NTHREADS 512

// A-fragment-packed fp16 W1 for mma.m16n8k16:
// jobs: 0..170 real = (m-1)*9+kb for m=1..19, kb=0..8; 171..179 zero pad.
// layout: [job(180)][jtile(4)][lane(32)] -> uint4 (8 halves in fragment order)
#define W1F_JOBS 180
#define W1F_U4   (W1F_JOBS * 4 * 32)
__device__ uint4 g_W1f[W1F_U4];

// ---- shared memory layout (float offsets) ----
#define RING_OFF   0        // fp32 newest row only: [4][144] = 576
#define RH_OFF     576      // fp16 B-fragment ring [20][9][32][4] halves = 11520 floats
#define W1A_OFF    12096    // m=0 weights fp32 [33 q][64 j][4 kk] = 8448
#define WHH_OFF    20544    // float4 layout [16 k][8 c][16 h][4 q] = 8192
#define WAIH_OFF   28736    // [2][16 k][64 gate] = 2048
#define WAHH_OFF   30784    // 2048
#define W2S_OFF    32832    // [16][68] = 1088
#define WIH_OFF    33920    // float4 [8 c][16 h][4 q] = 512
#define BE_OFF     34432    // float4 [8 c][16 h][4 q] = 512
#define PSB_OFF    34944    // GEMM-B partials [12 w][64 j][4 g] = 3072
#define OLDPS_OFF  38016    // [2 parity][64 j * 4 g] = 512
#define E1S_OFF    38528    // [4][64]
#define ZBUF_OFF   38784    // [4][64]
#define NC_OFF     39040    // [4][128]
#define B1S_OFF    39552    // 64
#define BAC_OFF    39616    // [2][64]
#define WGS_OFF    39744    // [8][16]
#define WOS_OFF    39872    // [8][16]
#define EHS_OFF    40000    // [4][16]
#define ECS_OFF    40064
#define AHS_OFF    40128    // [2][4][16]
#define ACS_OFF    40256
#define AIS_OFF    40384    // [4][16]
#define GSM_OFF    40448    // [4][8]
#define OSM_OFF    40480    // [4][8]
#define ERRH_OFF   40512    // [4][10]
#define B2S_OFF    40552
#define BGS_OFF    40568
#define BOS_OFF    40576
#define PRED_OFF   40584
#define THETA_OFF  40588
#define SMEM_FLOATS 40592
#define SMEM_BYTES  (SMEM_FLOATS * 4)

__device__ __forceinline__ float sigf(float v) {
    return __fdividef(1.0f, 1.0f + __expf(-v));
}
__device__ __forceinline__ float tanh2(float v) {
    return 1.0f - __fdividef(2.0f, __expf(2.0f * v) + 1.0f);
}

// Build fragment-ordered fp16 weights for mma.m16n8k16 (A, row-major 16x16 tiles)
__global__ void build_w1f(const float* __restrict__ W1) {
    int idx = blockIdx.x * 256 + threadIdx.x;
    if (idx >= W1F_U4) return;
    int lane = idx & 31;
    int jt   = (idx >> 5) & 3;
    int job  = idx >> 7;
    int r  = lane >> 2;
    int tg = lane & 3;
    float f[8];
    #pragma unroll
    for (int i = 0; i < 8; ++i) f[i] = 0.0f;
    if (job < 171) {
        int m  = 1 + job / 9;
        int kb = job - (m - 1) * 9;
        int j0 = jt * 16;
        int kbase = kb * 16;
        const int dj[8] = {r, r, r + 8, r + 8, r, r, r + 8, r + 8};
        const int dc[8] = {2*tg, 2*tg+1, 2*tg, 2*tg+1, 2*tg+8, 2*tg+9, 2*tg+8, 2*tg+9};
        #pragma unroll
        for (int i = 0; i < 8; ++i) {
            int kc = kbase + dc[i];
            if (kc < 129) f[i] = W1[(j0 + dj[i]) * 2580 + m * 129 + kc];
        }
    }
    __half h[8];
    #pragma unroll
    for (int i = 0; i < 8; ++i) h[i] = __float2half(f[i]);
    uint4 u;
    u.x = *reinterpret_cast<unsigned int*>(&h[0]);
    u.y = *reinterpret_cast<unsigned int*>(&h[2]);
    u.z = *reinterpret_cast<unsigned int*>(&h[4]);
    u.w = *reinterpret_cast<unsigned int*>(&h[6]);
    g_W1f[idx] = u;
}

#define MMA16816(d, a, bx, by) \
    asm volatile("mma.sync.aligned.m16n8k16.row.col.f32.f16.f16.f32 " \
        "{%0,%1,%2,%3}, {%4,%5,%6,%7}, {%8,%9}, {%0,%1,%2,%3};" \
        : "+f"(d[0]), "+f"(d[1]), "+f"(d[2]), "+f"(d[3]) \
        : "r"(a.x), "r"(a.y), "r"(a.z), "r"(a.w), "r"(bx), "r"(by))

__global__ __launch_bounds__(NTHREADS, 1)
void mmoe_main(
    const float* __restrict__ x,      const float* __restrict__ pred0,
    const float* __restrict__ gate0,
    const float* __restrict__ W_ih,   const float* __restrict__ W_hh,
    const float* __restrict__ b_ih,   const float* __restrict__ b_hh,
    const float* __restrict__ W_o,    const float* __restrict__ b_o,
    const float* __restrict__ W1,     const float* __restrict__ b1,
    const float* __restrict__ W2,     const float* __restrict__ b2,
    const float* __restrict__ Wg,     const float* __restrict__ bg,
    const float* __restrict__ Wa_ih,  const float* __restrict__ Wa_hh,
    const float* __restrict__ ba_ih,  const float* __restrict__ ba_hh,
    float* __restrict__ out)
{
    extern __shared__ float sm[];
    __half* rh = reinterpret_cast<__half*>(&sm[RH_OFF]);
    const int tid = threadIdx.x;
    const int b0  = blockIdx.x * G;

    // ---------- init shared ----------
    if (tid < 576) {
        int pos = tid % 144;
        sm[RING_OFF + tid] = (pos == 128) ? 0.5f : 0.0f;
    }
    for (int i = tid; i < 23040; i += NTHREADS) {
        int q = i & 3, ln = (i >> 2) & 31, kb = (i >> 7) % 9;
        bool is05 = (q == 0) && ((ln & 3) == 0) && (ln < 16) && (kb == 8);
        rh[i] = __float2half(is05 ? 0.5f : 0.0f);
    }
    for (int i = tid; i < 8448; i += NTHREADS) {
        int kk = i & 3, jj = (i >> 2) & 63, q = i >> 8;
        int k = q * 4 + kk;
        sm[W1A_OFF + i] = (k < 129) ? W1[jj * 2580 + k] : 0.0f;
    }
    for (int i = tid; i < 8192; i += NTHREADS) {
        int q = i & 3, h = (i >> 2) & 15, c = (i >> 6) & 7, k = i >> 9;
        sm[WHH_OFF + i] = W_hh[(c * 64 + q * 16 + h) * 16 + k];
    }
    for (int i = tid; i < 2048; i += NTHREADS) {
        int l = i >> 10, r = i & 1023, k = r >> 6, gate = r & 63;
        sm[WAIH_OFF + i] = Wa_ih[l * 1024 + gate * 16 + k];
        sm[WAHH_OFF + i] = Wa_hh[l * 1024 + gate * 16 + k];
    }
    for (int i = tid; i < 1088; i += NTHREADS) {
        int j2 = i / 68, k = i - j2 * 68;
        sm[W2S_OFF + i] = (k < 64) ? W2[j2 * 64 + k] : 0.0f;
    }
    if (tid < 512) {
        int q = tid & 3, h = (tid >> 2) & 15, c = tid >> 6;
        int gidx = c * 64 + q * 16 + h;
        sm[WIH_OFF + tid] = W_ih[gidx];
        sm[BE_OFF + tid]  = b_ih[gidx] + b_hh[gidx];
    }
    if (tid < 256) {
        int jj = tid >> 2, gg = tid & 3;
        float sacc = 0.0f;
        for (int m = 1; m < 20; ++m) sacc += W1[jj * 2580 + m * 129 + 128];
        sm[OLDPS_OFF + jj * 4 + gg] = 0.5f * sacc;
    }
    if (tid < 128) {
        sm[BAC_OFF + tid] = ba_ih[tid] + ba_hh[tid];
        sm[WGS_OFF + tid] = Wg[tid];
        sm[WOS_OFF + tid] = W_o[tid];
        sm[AHS_OFF + tid] = 0.0f;
        sm[ACS_OFF + tid] = 0.0f;
    }
    if (tid < 64) { sm[B1S_OFF + tid] = b1[tid]; sm[EHS_OFF + tid] = 0.0f; sm[ECS_OFF + tid] = 0.0f; }
    if (tid < 40) sm[ERRH_OFF + tid] = 0.5f;
    if (tid < 32) sm[GSM_OFF + tid] = gate0[b0 * 8 + tid];
    if (tid < 16) sm[B2S_OFF + tid] = b2[tid];
    if (tid < 8)  { sm[BGS_OFF + tid] = bg[tid]; sm[BOS_OFF + tid] = b_o[tid]; }
    if (tid < 4)  sm[PRED_OFF + tid] = pred0[b0 + tid];
    __syncthreads();

    int head = 0;

    for (int t = 0; t < NSTEP; ++t) {
        int s = head - 1; if (s < 0) s = 19;   // nh_slot

        if (tid < 128) {
            // ================= small group: warps 0-3 =================
            // ---- phase 2: experts; thread (c,h) handles all 4 g ----
            {
                int c = tid >> 4, h = tid & 15;
                int ch4 = (c * 16 + h) * 4;
                float be[4], wi[4];
                *reinterpret_cast<float4*>(be) = *(const float4*)&sm[BE_OFF + ch4];
                *reinterpret_cast<float4*>(wi) = *(const float4*)&sm[WIH_OFF + ch4];
                float z[4][4];
                #pragma unroll
                for (int g = 0; g < 4; ++g) {
                    float xv = __ldg(&x[(b0 + g) * NSTEP + t]);
                    #pragma unroll
                    for (int q = 0; q < 4; ++q) z[g][q] = be[q] + xv * wi[q];
                }
                #pragma unroll
                for (int kq = 0; kq < 4; ++kq) {
                    float ev[4][4];
                    #pragma unroll
                    for (int g = 0; g < 4; ++g)
                        *reinterpret_cast<float4*>(ev[g]) =
                            *(const float4*)&sm[EHS_OFF + g * 16 + kq * 4];
                    #pragma unroll
                    for (int kk = 0; kk < 4; ++kk) {
                        int k = kq * 4 + kk;
                        float wv[4];
                        *reinterpret_cast<float4*>(wv) =
                            *(const float4*)&sm[WHH_OFF + ((k * 8 + c) * 16 + h) * 4];
                        #pragma unroll
                        for (int g = 0; g < 4; ++g) {
                            float e = ev[g][kk];
                            z[g][0] += e * wv[0];
                            z[g][1] += e * wv[1];
                            z[g][2] += e * wv[2];
                            z[g][3] += e * wv[3];
                        }
                    }
                }
                int lane = ((h & 7) >> 1);
                int q = (h & 1) | ((h >> 3) << 1);
                #pragma unroll
                for (int g = 0; g < 4; ++g) {
                    float ec = sm[ECS_OFF + g * 16 + h];
                    float c2 = sigf(z[g][1]) * ec + sigf(z[g][0]) * tanh2(z[g][2]);
                    float hn = sigf(z[g][3]) * tanh2(c2);
                    sm[RING_OFF + g * 144 + c * 16 + h] = hn;
                    sm[NC_OFF + g * 128 + c * 16 + h] = c2;
                    rh[((s * 9 + c) * 32 + ((g << 2) | lane)) * 4 + q] = __float2half(hn);
                }
            }
            if (tid < 4) {
                float xv = x[(b0 + tid) * NSTEP + t];
                float e = xv - sm[PRED_OFF + tid];
                sm[ERRH_OFF + tid * 10 + (t % 10)] = e;
                sm[RING_OFF + tid * 144 + 128] = e;
                rh[((s * 9 + 8) * 32 + (tid << 2)) * 4] = __float2half(e);
            }
            asm volatile("bar.sync 4, 512;" ::: "memory");   // ring slot s ready

            // ---- GEMM-A: new-row slice (m=0) + old partial -> e1 ----
            {
                int jA = tid & 63, gp = tid >> 6;
                const float4* wA = reinterpret_cast<const float4*>(&sm[W1A_OFF]);
                const float4* r4 = reinterpret_cast<const float4*>(sm);
                int rb0 = (2 * gp) * 36;
                int rb1 = (2 * gp + 1) * 36;
                float a0[4] = {0.f, 0.f, 0.f, 0.f};
                float a1[4] = {0.f, 0.f, 0.f, 0.f};
                #pragma unroll
                for (int q = 0; q < 33; ++q) {
                    float4 w  = wA[q * 64 + jA];
                    float4 v0 = r4[rb0 + q];
                    a0[q & 3] += w.x * v0.x + w.y * v0.y + w.z * v0.z + w.w * v0.w;
                    float4 v1 = r4[rb1 + q];
                    a1[q & 3] += w.x * v1.x + w.y * v1.y + w.z * v1.z + w.w * v1.w;
                }
                int par = (t & 1) * 256;
                float bb = sm[B1S_OFF + jA];
                float s0 = (a0[0] + a0[1]) + (a0[2] + a0[3]);
                float s1 = (a1[0] + a1[1]) + (a1[2] + a1[3]);
                sm[E1S_OFF + (2 * gp) * 64 + jA] =
                    fmaxf(s0 + sm[OLDPS_OFF + par + jA * 4 + 2 * gp] + bb, 0.0f);
                sm[E1S_OFF + (2 * gp + 1) * 64 + jA] =
                    fmaxf(s1 + sm[OLDPS_OFF + par + jA * 4 + 2 * gp + 1] + bb, 0.0f);
            }
            asm volatile("bar.sync 1, 128;" ::: "memory");

            // ---- phase 5: MLP2 | expert heads | theta ----
            if (tid < 64) {
                int g = tid >> 4, j2 = tid & 15;
                const float4* e4 = reinterpret_cast<const float4*>(&sm[E1S_OFF + g * 64]);
                const float4* w4 = reinterpret_cast<const float4*>(&sm[W2S_OFF + j2 * 68]);
                float a[4] = {0.f, 0.f, 0.f, 0.f};
                #pragma unroll
                for (int kq = 0; kq < 16; ++kq) {
                    float4 e = e4[kq];
                    float4 w = w4[kq];
                    a[kq & 3] += e.x * w.x + e.y * w.y + e.z * w.z + e.w * w.w;
                }
                float sacc = sm[B2S_OFF + j2] + (a[0] + a[1]) + (a[2] + a[3]);
                sm[AIS_OFF + g * 16 + j2] = fmaxf(sacc, 0.0f);
            } else if (tid < 96) {
                int u = tid - 64, g = u >> 3, c = u & 7;
                float sacc = sm[BOS_OFF + c];
                const float* rr = &sm[RING_OFF + g * 144 + c * 16];
                #pragma unroll
                for (int h = 0; h < 16; ++h) sacc += rr[h] * sm[WOS_OFF + c * 16 + h];
                sm[OSM_OFF + g * 8 + c] = sacc;
            } else if (tid < 100) {
                int g = tid - 96;
                float sacc = 0.0f;
                #pragma unroll
                for (int i2 = 0; i2 < 10; ++i2) sacc += fabsf(sm[ERRH_OFF + g * 10 + i2]);
                sm[THETA_OFF + g] = fminf(0.25f * sacc, 1.0f);
            }
            asm volatile("bar.sync 1, 128;" ::: "memory");

            // ---- phase 6: agent, 2 stacked LSTM layers ----
            #pragma unroll 1
            for (int l = 0; l < 2; ++l) {
                #pragma unroll
                for (int r = 0; r < 2; ++r) {
                    int e = tid + (r << 7);
                    int g = e >> 6, gate = e & 63;
                    const float* inp = (l == 0) ? &sm[AIS_OFF + g * 16]
                                                : &sm[AHS_OFF + g * 16];
                    const float* hp  = &sm[AHS_OFF + l * 64 + g * 16];
                    const float* wi = &sm[WAIH_OFF + l * 1024 + gate];
                    const float* wh = &sm[WAHH_OFF + l * 1024 + gate];
                    float za = sm[BAC_OFF + l * 64 + gate], zb = 0.0f;
                    #pragma unroll
                    for (int k = 0; k < 16; ++k) {
                        za += inp[k] * wi[k * 64];
                        zb += hp[k] * wh[k * 64];
                    }
                    sm[ZBUF_OFF + g * 64 + gate] = za + zb;
                }
                asm volatile("bar.sync 1, 128;" ::: "memory");
                if (tid < 64) {
                    int g2 = tid >> 4, h = tid & 15;
                    float zi = sm[ZBUF_OFF + g2 * 64 + h];
                    float zf = sm[ZBUF_OFF + g2 * 64 + 16 + h];
                    float zg = sm[ZBUF_OFF + g2 * 64 + 32 + h];
                    float zo = sm[ZBUF_OFF + g2 * 64 + 48 + h];
                    float c2 = sigf(zf) * sm[ACS_OFF + l * 64 + g2 * 16 + h]
                             + sigf(zi) * tanh2(zg);
                    float hn = sigf(zo) * tanh2(c2);
                    sm[ACS_OFF + l * 64 + g2 * 16 + h] = c2;
                    sm[AHS_OFF + l * 64 + g2 * 16 + h] = hn;
                }
                asm volatile("bar.sync 1, 128;" ::: "memory");
            }

            // ---- gate logits + softmax + blend + pred (one warp, shfl) ----
            if (tid < 32) {
                int g = tid >> 3, c = tid & 7;
                const float* a1p = &sm[AHS_OFF + 64 + g * 16];
                const float* wg  = &sm[WGS_OFF + c * 16];
                float za = sm[BGS_OFF + c], zb = 0.0f;
                #pragma unroll
                for (int k = 0; k < 8; ++k) {
                    za += a1p[2 * k] * wg[2 * k];
                    zb += a1p[2 * k + 1] * wg[2 * k + 1];
                }
                float zv = za + zb;
                float mx = zv;
                #pragma unroll
                for (int d = 1; d < 8; d <<= 1)
                    mx = fmaxf(mx, __shfl_xor_sync(0xffffffffu, mx, d));
                float ex = __expf(zv - mx);
                float ssum = ex;
                #pragma unroll
                for (int d = 1; d < 8; d <<= 1)
                    ssum += __shfl_xor_sync(0xffffffffu, ssum, d);
                float th = sm[THETA_OFF + g];
                float gf = ex * __fdividef(th, ssum)
                         + sm[GSM_OFF + g * 8 + c] * (1.0f - th);
                sm[GSM_OFF + g * 8 + c] = gf;
                float pv = gf * sm[OSM_OFF + g * 8 + c];
                #pragma unroll
                for (int d = 1; d < 8; d <<= 1)
                    pv += __shfl_xor_sync(0xffffffffu, pv, d);
                if (c == 0) {
                    sm[PRED_OFF + g] = pv;
                    out[(b0 + g) * NSTEP + t] = pv;
                }
            }
            asm volatile("bar.sync 1, 128;" ::: "memory");

            // ---- phase 7c: eh2 / ec2 ----
            if (tid < 64) {
                int g = tid >> 4, h = tid & 15;
                const float* rr = &sm[RING_OFF + g * 144];
                const float* nc = &sm[NC_OFF + g * 128];
                float se = 0.0f, sc = 0.0f;
                #pragma unroll
                for (int c = 0; c < 8; ++c) {
                    float gf = sm[GSM_OFF + g * 8 + c];
                    se += gf * rr[c * 16 + h];
                    sc += gf * nc[c * 16 + h];
                }
                sm[EHS_OFF + g * 16 + h] = se;
                sm[ECS_OFF + g * 16 + h] = sc;
            }
        } else {
            // ========== GEMM-B: warps 4-15, tensor cores, phase-2 overlapped ==========
            const int w    = (tid >> 5) - 4;   // 0..11
            const int lane = tid & 31;

            float d0[4], d1[4], d2[4], d3[4];
            #pragma unroll
            for (int i = 0; i < 4; ++i) { d0[i]=0.f; d1[i]=0.f; d2[i]=0.f; d3[i]=0.f; }

            const unsigned int* __restrict__ rhU =
                reinterpret_cast<const unsigned int*>(rh);
            const int J0 = 9 + w * 14;
            int m  = 1 + J0 / 9;
            int kb = J0 - (m - 1) * 9;
            int slot = s + m - 1; if (slot >= 20) slot -= 20;
            const uint4* __restrict__ wp = g_W1f + J0 * 128 + lane;

            // pre-barrier: 14 jobs with m >= 2 (independent of this step's phase 2)
            #pragma unroll
            for (int it = 0; it < 14; ++it) {
                int bofs = ((slot * 9 + kb) * 32 + lane) * 2;
                unsigned int bx = rhU[bofs];
                unsigned int by = rhU[bofs + 1];
                uint4 a0 = wp[it * 128];
                uint4 a1 = wp[it * 128 + 32];
                uint4 a2 = wp[it * 128 + 64];
                uint4 a3 = wp[it * 128 + 96];
                MMA16816(d0, a0, bx, by);
                MMA16816(d1, a1, bx, by);
                MMA16816(d2, a2, bx, by);
                MMA16816(d3, a3, bx, by);
                ++kb; if (kb == 9) { kb = 0; ++slot; if (slot == 20) slot = 0; }
            }
            asm volatile("bar.sync 4, 512;" ::: "memory");   // wait for phase 2

            // post-barrier: m=1 jobs (kb = w) for warps 0..8
            if (w < 9) {
                int bofs = ((s * 9 + w) * 32 + lane) * 2;
                unsigned int bx = rhU[bofs];
                unsigned int by = rhU[bofs + 1];
                const uint4* wq = g_W1f + w * 128 + lane;
                uint4 a0 = wq[0];
                uint4 a1 = wq[32];
                uint4 a2 = wq[64];
                uint4 a3 = wq[96];
                MMA16816(d0, a0, bx, by);
                MMA16816(d1, a1, bx, by);
                MMA16816(d2, a2, bx, by);
                MMA16816(d3, a3, bx, by);
            }
            // epilogue: lanes with tg<2 hold the real g columns
            {
                int tg = lane & 3, gr = lane >> 2;
                if (tg < 2) {
                    float* pb = &sm[PSB_OFF + (w * 64) * 4 + 2 * tg];
                    pb[(gr     ) * 4] = d0[0]; pb[(gr     ) * 4 + 1] = d0[1];
                    pb[(gr +  8) * 4] = d0[2]; pb[(gr +  8) * 4 + 1] = d0[3];
                    pb[(gr + 16) * 4] = d1[0]; pb[(gr + 16) * 4 + 1] = d1[1];
                    pb[(gr + 24) * 4] = d1[2]; pb[(gr + 24) * 4 + 1] = d1[3];
                    pb[(gr + 32) * 4] = d2[0]; pb[(gr + 32) * 4 + 1] = d2[1];
                    pb[(gr + 40) * 4] = d2[2]; pb[(gr + 40) * 4 + 1] = d2[3];
                    pb[(gr + 48) * 4] = d3[0]; pb[(gr + 48) * 4 + 1] = d3[1];
                    pb[(gr + 56) * 4] = d3[2]; pb[(gr + 56) * 4 + 1] = d3[3];
                }
            }
            asm volatile("bar.sync 2, 384;" ::: "memory");
            {
                int r = tid - 128;
                if (r < 256) {
                    int jr = r >> 2, gr = r & 3;
                    float sacc = 0.0f;
                    #pragma unroll
                    for (int c = 0; c < 12; ++c)
                        sacc += sm[PSB_OFF + (c * 64 + jr) * 4 + gr];
                    sm[OLDPS_OFF + ((t + 1) & 1) * 256 + jr * 4 + gr] = sacc;
                }
            }
        }
        __syncthreads();

        head = s;
    }
}

extern "C" void kernel_launch(void* const* d_in, const int* in_sizes, int n_in,
                              void* d_out, int out_size) {
    const float* x      = (const float*)d_in[0];
    const float* pred0  = (const float*)d_in[1];
    const float* gate0  = (const float*)d_in[2];
    const float* W_ih   = (const float*)d_in[3];
    const float* W_hh   = (const float*)d_in[4];
    const float* b_ih   = (const float*)d_in[5];
    const float* b_hh   = (const float*)d_in[6];
    const float* W_o    = (const float*)d_in[7];
    const float* b_o    = (const float*)d_in[8];
    const float* W1     = (const float*)d_in[9];
    const float* b1     = (const float*)d_in[10];
    const float* W2     = (const float*)d_in[11];
    const float* b2     = (const float*)d_in[12];
    const float* Wg     = (const float*)d_in[13];
    const float* bg     = (const float*)d_in[14];
    const float* Wa_ih  = (const float*)d_in[15];
    const float* Wa_hh  = (const float*)d_in[16];
    const float* ba_ih  = (const float*)d_in[17];
    const float* ba_hh  = (const float*)d_in[18];
    float* out = (float*)d_out;

    cudaFuncSetAttribute(mmoe_main, cudaFuncAttributeMaxDynamicSharedMemorySize, SMEM_BYTES);

    build_w1f<<<(W1F_U4 + 255) / 256, 256>>>(W1);
    mmoe_main<<<NCTA, NTHREADS, SMEM_BYTES>>>(
        x, pred0, gate0, W_ih, W_hh, b_ih, b_hh, W_o, b_o,
        W1, b1, W2, b2, Wg, bg, Wa_ih, Wa_hh, ba_ih, ba_hh, out);
}

// round 9
// speedup vs baseline: 2.2260x; 1.0227x over previous
#include <cuda_runtime.h>
#include <cuda_fp16.h>
#include <math.h>

#define NSTEP 256
#define G 4
#define NCTA 128
#define NTHREADS 512

// A-fragment-packed fp16 W1 for mma.m16n8k16:
// job = m*9+kb for m=0..19, kb=0..8 (180 real); jobs 180..185 zero pad.
// layout: [job(186)][jtile(4)][lane(32)] -> uint4 (8 halves in fragment order)
#define W1F_JOBS 186
#define W1F_U4   (W1F_JOBS * 4 * 32)
__device__ uint4 g_W1f[W1F_U4];

// ---- shared memory layout (float offsets) ----
#define RING_OFF   0        // fp32 newest nh row: [4][128] = 512
#define RH_OFF     512      // fp16 B-fragment ring [20][9][32][4] halves = 11520 floats
#define WHH_OFF    12032    // float4 layout [16 k][8 c][16 h][4 q] = 8192
#define WAIH_OFF   20224    // raw [2][64 gate][16 k] = 2048
#define WAHH_OFF   22272    // 2048
#define W2S_OFF    24320    // [16][68] = 1088
#define WIH_OFF    25408    // float4 [8 c][16 h][4 q] = 512
#define BE_OFF     25920    // 512
#define PSB_OFF    26432    // m>=1 partials [12 w][64 j][4 g] = 3072
#define PSA_OFF    29504    // m=0 partials [9 w][64 j][4 g] = 2304
#define OLDPS_OFF  31808    // [2 parity][64 j * 4 g] = 512
#define E1S_OFF    32320    // [4][64]
#define NC_OFF     32576    // [4][128]
#define B1S_OFF    33088    // 64
#define BAC_OFF    33152    // [2][64]
#define WGS_OFF    33280    // [8][16]
#define WOS_OFF    33408    // [8][16]
#define EHS_OFF    33536    // [4][16]
#define ECS_OFF    33600
#define AHS_OFF    33664    // [2][4][16]
#define ACS_OFF    33792
#define AIS_OFF    33920    // [4][16]
#define GSM_OFF    33984    // [4][8]
#define OSM_OFF    34016    // [4][8]
#define ERRH_OFF   34048    // [4][10]
#define B2S_OFF    34088
#define BGS_OFF    34104
#define BOS_OFF    34112
#define PRED_OFF   34120
#define THETA_OFF  34124
#define SMEM_FLOATS 34128
#define SMEM_BYTES  (SMEM_FLOATS * 4)

__device__ __forceinline__ float sigf(float v) {
    return __fdividef(1.0f, 1.0f + __expf(-v));
}
__device__ __forceinline__ float tanh2(float v) {
    return 1.0f - __fdividef(2.0f, __expf(2.0f * v) + 1.0f);
}

__global__ void build_w1f(const float* __restrict__ W1) {
    int idx = blockIdx.x * 256 + threadIdx.x;
    if (idx >= W1F_U4) return;
    int lane = idx & 31;
    int jt   = (idx >> 5) & 3;
    int job  = idx >> 7;
    int r  = lane >> 2;
    int tg = lane & 3;
    float f[8];
    #pragma unroll
    for (int i = 0; i < 8; ++i) f[i] = 0.0f;
    if (job < 180) {
        int m  = job / 9;
        int kb = job - m * 9;
        int j0 = jt * 16;
        int kbase = kb * 16;
        const int dj[8] = {r, r, r + 8, r + 8, r, r, r + 8, r + 8};
        const int dc[8] = {2*tg, 2*tg+1, 2*tg, 2*tg+1, 2*tg+8, 2*tg+9, 2*tg+8, 2*tg+9};
        #pragma unroll
        for (int i = 0; i < 8; ++i) {
            int kc = kbase + dc[i];
            if (kc < 129) f[i] = W1[(j0 + dj[i]) * 2580 + m * 129 + kc];
        }
    }
    __half h[8];
    #pragma unroll
    for (int i = 0; i < 8; ++i) h[i] = __float2half(f[i]);
    uint4 u;
    u.x = *reinterpret_cast<unsigned int*>(&h[0]);
    u.y = *reinterpret_cast<unsigned int*>(&h[2]);
    u.z = *reinterpret_cast<unsigned int*>(&h[4]);
    u.w = *reinterpret_cast<unsigned int*>(&h[6]);
    g_W1f[idx] = u;
}

#define MMA16816(d, a, bx, by) \
    asm volatile("mma.sync.aligned.m16n8k16.row.col.f32.f16.f16.f32 " \
        "{%0,%1,%2,%3}, {%4,%5,%6,%7}, {%8,%9}, {%0,%1,%2,%3};" \
        : "+f"(d[0]), "+f"(d[1]), "+f"(d[2]), "+f"(d[3]) \
        : "r"(a.x), "r"(a.y), "r"(a.z), "r"(a.w), "r"(bx), "r"(by))

// 14 pre-barrier jobs (m>=2) for the step whose nh-slot is sP.
__device__ __forceinline__ void prejobs(int sP, int w, int lane,
    const unsigned int* __restrict__ rhU,
    float (&d0)[4], float (&d1)[4], float (&d2)[4], float (&d3)[4])
{
    int J0 = 18 + w * 14;
    int m  = J0 / 9;
    int kb = J0 - m * 9;
    int slot = sP + m - 1;
    if (slot >= 20) slot -= 20;
    const uint4* __restrict__ wp = g_W1f + J0 * 128 + lane;
    #pragma unroll
    for (int it = 0; it < 14; ++it) {
        int bofs = ((slot * 9 + kb) * 32 + lane) * 2;
        unsigned int bx = rhU[bofs], by = rhU[bofs + 1];
        uint4 a0 = wp[it * 128];
        uint4 a1 = wp[it * 128 + 32];
        uint4 a2 = wp[it * 128 + 64];
        uint4 a3 = wp[it * 128 + 96];
        MMA16816(d0, a0, bx, by);
        MMA16816(d1, a1, bx, by);
        MMA16816(d2, a2, bx, by);
        MMA16816(d3, a3, bx, by);
        ++kb; if (kb == 9) { kb = 0; ++slot; if (slot == 20) slot = 0; }
    }
}

__global__ __launch_bounds__(NTHREADS, 1)
void mmoe_main(
    const float* __restrict__ x,      const float* __restrict__ pred0,
    const float* __restrict__ gate0,
    const float* __restrict__ W_ih,   const float* __restrict__ W_hh,
    const float* __restrict__ b_ih,   const float* __restrict__ b_hh,
    const float* __restrict__ W_o,    const float* __restrict__ b_o,
    const float* __restrict__ W1,     const float* __restrict__ b1,
    const float* __restrict__ W2,     const float* __restrict__ b2,
    const float* __restrict__ Wg,     const float* __restrict__ bg,
    const float* __restrict__ Wa_ih,  const float* __restrict__ Wa_hh,
    const float* __restrict__ ba_ih,  const float* __restrict__ ba_hh,
    float* __restrict__ out)
{
    extern __shared__ float sm[];
    __half* rh = reinterpret_cast<__half*>(&sm[RH_OFF]);
    const int tid = threadIdx.x;
    const int b0  = blockIdx.x * G;

    // ---------- init shared ----------
    if (tid < 512) sm[RING_OFF + tid] = 0.0f;
    for (int i = tid; i < 23040; i += NTHREADS) {
        int q = i & 3, ln = (i >> 2) & 31, kb = (i >> 7) % 9;
        bool is05 = (q == 0) && ((ln & 3) == 0) && (ln < 16) && (kb == 8);
        rh[i] = __float2half(is05 ? 0.5f : 0.0f);
    }
    for (int i = tid; i < 8192; i += NTHREADS) {
        int q = i & 3, h = (i >> 2) & 15, c = (i >> 6) & 7, k = i >> 9;
        sm[WHH_OFF + i] = W_hh[(c * 64 + q * 16 + h) * 16 + k];
    }
    for (int i = tid; i < 2048; i += NTHREADS) {
        sm[WAIH_OFF + i] = Wa_ih[i];
        sm[WAHH_OFF + i] = Wa_hh[i];
    }
    for (int i = tid; i < 1088; i += NTHREADS) {
        int j2 = i / 68, k = i - j2 * 68;
        sm[W2S_OFF + i] = (k < 64) ? W2[j2 * 64 + k] : 0.0f;
    }
    if (tid < 512) {
        int q = tid & 3, h = (tid >> 2) & 15, c = tid >> 6;
        int gidx = c * 64 + q * 16 + h;
        sm[WIH_OFF + tid] = W_ih[gidx];
        sm[BE_OFF + tid]  = b_ih[gidx] + b_hh[gidx];
    }
    if (tid < 256) {
        int jj = tid >> 2, gg = tid & 3;
        float sacc = 0.0f;
        for (int m = 1; m < 20; ++m) sacc += W1[jj * 2580 + m * 129 + 128];
        sm[OLDPS_OFF + jj * 4 + gg] = 0.5f * sacc;
    }
    if (tid < 128) {
        sm[BAC_OFF + tid] = ba_ih[tid] + ba_hh[tid];
        sm[WGS_OFF + tid] = Wg[tid];
        sm[WOS_OFF + tid] = W_o[tid];
        sm[AHS_OFF + tid] = 0.0f;
        sm[ACS_OFF + tid] = 0.0f;
    }
    if (tid < 64) { sm[B1S_OFF + tid] = b1[tid]; sm[EHS_OFF + tid] = 0.0f; sm[ECS_OFF + tid] = 0.0f; }
    if (tid < 40) sm[ERRH_OFF + tid] = 0.5f;
    if (tid < 32) sm[GSM_OFF + tid] = gate0[b0 * 8 + tid];
    if (tid < 16) sm[B2S_OFF + tid] = b2[tid];
    if (tid < 8)  { sm[BGS_OFF + tid] = bg[tid]; sm[BOS_OFF + tid] = b_o[tid]; }
    if (tid < 4)  sm[PRED_OFF + tid] = pred0[b0 + tid];
    __syncthreads();

    if (tid < 128) {
        // ====================== SMALL GROUP: warps 0-3 ======================
        int head = 0;
        for (int t = 0; t < NSTEP; ++t) {
            int s = head - 1; if (s < 0) s = 19;

            // ---- phase 2: experts; thread (c,h) handles all 4 g ----
            {
                int c = tid >> 4, h = tid & 15;
                int ch4 = (c * 16 + h) * 4;
                float be[4], wi[4];
                *reinterpret_cast<float4*>(be) = *(const float4*)&sm[BE_OFF + ch4];
                *reinterpret_cast<float4*>(wi) = *(const float4*)&sm[WIH_OFF + ch4];
                float z[4][4];
                #pragma unroll
                for (int g = 0; g < 4; ++g) {
                    float xv = __ldg(&x[(b0 + g) * NSTEP + t]);
                    #pragma unroll
                    for (int q = 0; q < 4; ++q) z[g][q] = be[q] + xv * wi[q];
                }
                #pragma unroll
                for (int kq = 0; kq < 4; ++kq) {
                    float ev[4][4];
                    #pragma unroll
                    for (int g = 0; g < 4; ++g)
                        *reinterpret_cast<float4*>(ev[g]) =
                            *(const float4*)&sm[EHS_OFF + g * 16 + kq * 4];
                    #pragma unroll
                    for (int kk = 0; kk < 4; ++kk) {
                        int k = kq * 4 + kk;
                        float wv[4];
                        *reinterpret_cast<float4*>(wv) =
                            *(const float4*)&sm[WHH_OFF + ((k * 8 + c) * 16 + h) * 4];
                        #pragma unroll
                        for (int g = 0; g < 4; ++g) {
                            float e = ev[g][kk];
                            z[g][0] += e * wv[0];
                            z[g][1] += e * wv[1];
                            z[g][2] += e * wv[2];
                            z[g][3] += e * wv[3];
                        }
                    }
                }
                int lane2 = ((h & 7) >> 1);
                int q2 = (h & 1) | ((h >> 3) << 1);
                #pragma unroll
                for (int g = 0; g < 4; ++g) {
                    float ec = sm[ECS_OFF + g * 16 + h];
                    float c2 = sigf(z[g][1]) * ec + sigf(z[g][0]) * tanh2(z[g][2]);
                    float hn = sigf(z[g][3]) * tanh2(c2);
                    sm[RING_OFF + g * 128 + c * 16 + h] = hn;
                    sm[NC_OFF + g * 128 + c * 16 + h] = c2;
                    rh[((s * 9 + c) * 32 + ((g << 2) | lane2)) * 4 + q2] = __float2half(hn);
                }
            }
            if (tid < 4) {
                float xv = x[(b0 + tid) * NSTEP + t];
                float e = xv - sm[PRED_OFF + tid];
                sm[ERRH_OFF + tid * 10 + (t % 10)] = e;
                rh[((s * 9 + 8) * 32 + (tid << 2)) * 4] = __float2half(e);
            }
            asm volatile("bar.sync 4, 512;" ::: "memory");   // ring slot s ready

            // ---- heads + theta (hidden under GEMM post-jobs) ----
            if (tid < 32) {
                int g = tid >> 3, c = tid & 7;
                float sacc = sm[BOS_OFF + c];
                const float* rr = &sm[RING_OFF + g * 128 + c * 16];
                #pragma unroll
                for (int h = 0; h < 16; ++h) sacc += rr[h] * sm[WOS_OFF + c * 16 + h];
                sm[OSM_OFF + g * 8 + c] = sacc;
            } else if (tid < 36) {
                int g = tid - 32;
                float sacc = 0.0f;
                #pragma unroll
                for (int i2 = 0; i2 < 10; ++i2) sacc += fabsf(sm[ERRH_OFF + g * 10 + i2]);
                sm[THETA_OFF + g] = fminf(0.25f * sacc, 1.0f);
            }
            asm volatile("bar.sync 5, 512;" ::: "memory");   // E1S published

            if (tid < 64) {
                // ---- MLP2 ----
                int g = tid >> 4, j2 = tid & 15;
                {
                    const float4* e4 = reinterpret_cast<const float4*>(&sm[E1S_OFF + g * 64]);
                    const float4* w4 = reinterpret_cast<const float4*>(&sm[W2S_OFF + j2 * 68]);
                    float a[4] = {0.f, 0.f, 0.f, 0.f};
                    #pragma unroll
                    for (int kq = 0; kq < 16; ++kq) {
                        float4 e = e4[kq];
                        float4 w = w4[kq];
                        a[kq & 3] += e.x * w.x + e.y * w.y + e.z * w.z + e.w * w.w;
                    }
                    float sacc = sm[B2S_OFF + j2] + (a[0] + a[1]) + (a[2] + a[3]);
                    sm[AIS_OFF + g * 16 + j2] = fmaxf(sacc, 0.0f);
                }
                __syncwarp();
                // ---- agent: 2 fused LSTM layers, no intra-layer barriers ----
                int h = j2;
                #pragma unroll
                for (int l = 0; l < 2; ++l) {
                    const float* inp = (l == 0) ? &sm[AIS_OFF + g * 16]
                                                : &sm[AHS_OFF + g * 16];
                    const float* hp  = &sm[AHS_OFF + l * 64 + g * 16];
                    float iv[16], hv[16];
                    #pragma unroll
                    for (int kq = 0; kq < 4; ++kq) {
                        *reinterpret_cast<float4*>(&iv[kq * 4]) =
                            *(const float4*)&inp[kq * 4];
                        *reinterpret_cast<float4*>(&hv[kq * 4]) =
                            *(const float4*)&hp[kq * 4];
                    }
                    float z[4];
                    #pragma unroll
                    for (int q = 0; q < 4; ++q) {
                        const float4* wi4 = (const float4*)&sm[WAIH_OFF + l * 1024 + (q * 16 + h) * 16];
                        const float4* wh4 = (const float4*)&sm[WAHH_OFF + l * 1024 + (q * 16 + h) * 16];
                        float za = sm[BAC_OFF + l * 64 + q * 16 + h], zb = 0.0f;
                        #pragma unroll
                        for (int kq = 0; kq < 4; ++kq) {
                            float4 wi = wi4[kq], wh = wh4[kq];
                            za += iv[kq*4] * wi.x + iv[kq*4+1] * wi.y
                                + iv[kq*4+2] * wi.z + iv[kq*4+3] * wi.w;
                            zb += hv[kq*4] * wh.x + hv[kq*4+1] * wh.y
                                + hv[kq*4+2] * wh.z + hv[kq*4+3] * wh.w;
                        }
                        z[q] = za + zb;
                    }
                    float c2 = sigf(z[1]) * sm[ACS_OFF + l * 64 + g * 16 + h]
                             + sigf(z[0]) * tanh2(z[2]);
                    float hn = sigf(z[3]) * tanh2(c2);
                    sm[ACS_OFF + l * 64 + g * 16 + h] = c2;
                    sm[AHS_OFF + l * 64 + g * 16 + h] = hn;
                    __syncwarp();
                }
            }
            asm volatile("bar.sync 1, 128;" ::: "memory");

            // ---- gate logits + softmax + blend + pred + eh2/ec2 (one warp) ----
            if (tid < 32) {
                int g = tid >> 3, c = tid & 7;
                const float* a1p = &sm[AHS_OFF + 64 + g * 16];
                const float* wg  = &sm[WGS_OFF + c * 16];
                float za = sm[BGS_OFF + c], zb = 0.0f;
                #pragma unroll
                for (int k = 0; k < 8; ++k) {
                    za += a1p[2 * k] * wg[2 * k];
                    zb += a1p[2 * k + 1] * wg[2 * k + 1];
                }
                float zv = za + zb;
                float mx = zv;
                #pragma unroll
                for (int d = 1; d < 8; d <<= 1)
                    mx = fmaxf(mx, __shfl_xor_sync(0xffffffffu, mx, d));
                float ex = __expf(zv - mx);
                float ssum = ex;
                #pragma unroll
                for (int d = 1; d < 8; d <<= 1)
                    ssum += __shfl_xor_sync(0xffffffffu, ssum, d);
                float th = sm[THETA_OFF + g];
                float gf = ex * __fdividef(th, ssum)
                         + sm[GSM_OFF + g * 8 + c] * (1.0f - th);
                sm[GSM_OFF + g * 8 + c] = gf;
                float pv = gf * sm[OSM_OFF + g * 8 + c];
                #pragma unroll
                for (int d = 1; d < 8; d <<= 1)
                    pv += __shfl_xor_sync(0xffffffffu, pv, d);
                if (c == 0) {
                    sm[PRED_OFF + g] = pv;
                    out[(b0 + g) * NSTEP + t] = pv;
                }
                // eh2/ec2: lane (g,c) computes h = 2c, 2c+1
                const float* rr = &sm[RING_OFF + g * 128];
                const float* nc = &sm[NC_OFF + g * 128];
                float se0 = 0.f, se1 = 0.f, sc0 = 0.f, sc1 = 0.f;
                #pragma unroll
                for (int cc = 0; cc < 8; ++cc) {
                    float gfb = __shfl_sync(0xffffffffu, gf, (g << 3) | cc);
                    se0 += gfb * rr[cc * 16 + 2 * c];
                    se1 += gfb * rr[cc * 16 + 2 * c + 1];
                    sc0 += gfb * nc[cc * 16 + 2 * c];
                    sc1 += gfb * nc[cc * 16 + 2 * c + 1];
                }
                sm[EHS_OFF + g * 16 + 2 * c]     = se0;
                sm[EHS_OFF + g * 16 + 2 * c + 1] = se1;
                sm[ECS_OFF + g * 16 + 2 * c]     = sc0;
                sm[ECS_OFF + g * 16 + 2 * c + 1] = sc1;
            }
            asm volatile("bar.sync 1, 128;" ::: "memory");

            head = s;
        }
    } else {
        // ====================== GEMM GROUP: warps 4-15 ======================
        const int w    = (tid >> 5) - 4;   // 0..11
        const int lane = tid & 31;
        const unsigned int* __restrict__ rhU =
            reinterpret_cast<const unsigned int*>(rh);

        float d0[4] = {0,0,0,0}, d1[4] = {0,0,0,0};
        float d2[4] = {0,0,0,0}, d3[4] = {0,0,0,0};
        prejobs(19, w, lane, rhU, d0, d1, d2, d3);   // m>=2 jobs for t=0

        int head = 0;
        for (int t = 0; t < NSTEP; ++t) {
            int s = head - 1; if (s < 0) s = 19;
            asm volatile("bar.sync 4, 512;" ::: "memory");   // slot s ready

            float e0[4] = {0,0,0,0}, e1[4] = {0,0,0,0};
            float e2[4] = {0,0,0,0}, e3[4] = {0,0,0,0};
            if (w < 9) {
                // m=1 job (kb=w) -> accumulate into d (partial for t+1)
                int bofs = ((s * 9 + w) * 32 + lane) * 2;
                unsigned int bx = rhU[bofs], by = rhU[bofs + 1];
                const uint4* wq = g_W1f + (9 + w) * 128 + lane;
                uint4 a0 = wq[0], a1 = wq[32], a2 = wq[64], a3 = wq[96];
                MMA16816(d0, a0, bx, by);
                MMA16816(d1, a1, bx, by);
                MMA16816(d2, a2, bx, by);
                MMA16816(d3, a3, bx, by);
            }
            if (w >= 3) {
                // m=0 job (kb=w-3) -> fresh accumulators (e1 of THIS step)
                int kb0 = w - 3;
                int bofs = ((s * 9 + kb0) * 32 + lane) * 2;
                unsigned int bx = rhU[bofs], by = rhU[bofs + 1];
                const uint4* wq = g_W1f + kb0 * 128 + lane;
                uint4 a0 = wq[0], a1 = wq[32], a2 = wq[64], a3 = wq[96];
                MMA16816(e0, a0, bx, by);
                MMA16816(e1, a1, bx, by);
                MMA16816(e2, a2, bx, by);
                MMA16816(e3, a3, bx, by);
            }
            // epilogue
            {
                int tg = lane & 3, gr = lane >> 2;
                if (tg < 2) {
                    float* pb = &sm[PSB_OFF + (w * 64) * 4 + 2 * tg];
                    pb[(gr     ) * 4] = d0[0]; pb[(gr     ) * 4 + 1] = d0[1];
                    pb[(gr +  8) * 4] = d0[2]; pb[(gr +  8) * 4 + 1] = d0[3];
                    pb[(gr + 16) * 4] = d1[0]; pb[(gr + 16) * 4 + 1] = d1[1];
                    pb[(gr + 24) * 4] = d1[2]; pb[(gr + 24) * 4 + 1] = d1[3];
                    pb[(gr + 32) * 4] = d2[0]; pb[(gr + 32) * 4 + 1] = d2[1];
                    pb[(gr + 40) * 4] = d2[2]; pb[(gr + 40) * 4 + 1] = d2[3];
                    pb[(gr + 48) * 4] = d3[0]; pb[(gr + 48) * 4 + 1] = d3[1];
                    pb[(gr + 56) * 4] = d3[2]; pb[(gr + 56) * 4 + 1] = d3[3];
                    if (w >= 3) {
                        float* pa = &sm[PSA_OFF + ((w - 3) * 64) * 4 + 2 * tg];
                        pa[(gr     ) * 4] = e0[0]; pa[(gr     ) * 4 + 1] = e0[1];
                        pa[(gr +  8) * 4] = e0[2]; pa[(gr +  8) * 4 + 1] = e0[3];
                        pa[(gr + 16) * 4] = e1[0]; pa[(gr + 16) * 4 + 1] = e1[1];
                        pa[(gr + 24) * 4] = e1[2]; pa[(gr + 24) * 4 + 1] = e1[3];
                        pa[(gr + 32) * 4] = e2[0]; pa[(gr + 32) * 4 + 1] = e2[1];
                        pa[(gr + 40) * 4] = e2[2]; pa[(gr + 40) * 4 + 1] = e2[3];
                        pa[(gr + 48) * 4] = e3[0]; pa[(gr + 48) * 4 + 1] = e3[1];
                        pa[(gr + 56) * 4] = e3[2]; pa[(gr + 56) * 4 + 1] = e3[3];
                    }
                }
            }
            asm volatile("bar.sync 2, 384;" ::: "memory");
            // reduce: OLDPS (next step) and E1S (this step)
            {
                int r = tid - 128;
                if (r < 256) {
                    int jr = r >> 2, gr = r & 3;
                    float s12 = 0.0f;
                    #pragma unroll
                    for (int c = 0; c < 12; ++c)
                        s12 += sm[PSB_OFF + (c * 64 + jr) * 4 + gr];
                    sm[OLDPS_OFF + ((t + 1) & 1) * 256 + jr * 4 + gr] = s12;
                    float s9 = sm[OLDPS_OFF + (t & 1) * 256 + jr * 4 + gr] + sm[B1S_OFF + jr];
                    #pragma unroll
                    for (int c = 0; c < 9; ++c)
                        s9 += sm[PSA_OFF + (c * 64 + jr) * 4 + gr];
                    sm[E1S_OFF + gr * 64 + jr] = fmaxf(s9, 0.0f);
                }
            }
            asm volatile("bar.sync 5, 512;" ::: "memory");   // publish E1S

            #pragma unroll
            for (int i = 0; i < 4; ++i) { d0[i] = 0.f; d1[i] = 0.f; d2[i] = 0.f; d3[i] = 0.f; }
            if (t < NSTEP - 1) {
                int s1 = s - 1; if (s1 < 0) s1 = 19;
                prejobs(s1, w, lane, rhU, d0, d1, d2, d3);   // m>=2 jobs for t+1
            }
            head = s;
        }
    }
}

extern "C" void kernel_launch(void* const* d_in, const int* in_sizes, int n_in,
                              void* d_out, int out_size) {
    const float* x      = (const float*)d_in[0];
    const float* pred0  = (const float*)d_in[1];
    const float* gate0  = (const float*)d_in[2];
    const float* W_ih   = (const float*)d_in[3];
    const float* W_hh   = (const float*)d_in[4];
    const float* b_ih   = (const float*)d_in[5];
    const float* b_hh   = (const float*)d_in[6];
    const float* W_o    = (const float*)d_in[7];
    const float* b_o    = (const float*)d_in[8];
    const float* W1     = (const float*)d_in[9];
    const float* b1     = (const float*)d_in[10];
    const float* W2     = (const float*)d_in[11];
    const float* b2     = (const float*)d_in[12];
    const float* Wg     = (const float*)d_in[13];
    const float* bg     = (const float*)d_in[14];
    const float* Wa_ih  = (const float*)d_in[15];
    const float* Wa_hh  = (const float*)d_in[16];
    const float* ba_ih  = (const float*)d_in[17];
    const float* ba_hh  = (const float*)d_in[18];
    float* out = (float*)d_out;

    cudaFuncSetAttribute(mmoe_main, cudaFuncAttributeMaxDynamicSharedMemorySize, SMEM_BYTES);

    build_w1f<<<(W1F_U4 + 255) / 256, 256>>>(W1);
    mmoe_main<<<NCTA, NTHREADS, SMEM_BYTES>>>(
        x, pred0, gate0, W_ih, W_hh, b_ih, b_hh, W_o, b_o,
        W1, b1, W2, b2, Wg, bg, Wa_ih, Wa_hh, ba_ih, ba_hh, out);
}

// round 10
// speedup vs baseline: 2.2714x; 1.0204x over previous
#include <cuda_runtime.h>
#include <cuda_fp16.h>
#include <math.h>

#define NSTEP 256
#define G 4
#define NCTA 128
#define NTHREADS 512

// A-fragment-packed fp16 W1 for mma.m16n8k16:
// job = m*9+kb for m=0..19, kb=0..8 (180 real); jobs 180..185 zero pad.
// layout: [job(186)][jtile(4)][lane(32)] -> uint4 (8 halves in fragment order)
#define W1F_JOBS 186
#define W1F_U4   (W1F_JOBS * 4 * 32)
__device__ uint4 g_W1f[W1F_U4];

// ---- shared memory layout (float offsets) ----
#define RING_OFF   0        // fp32 newest nh row: [4][128] = 512
#define RH_OFF     512      // fp16 B-fragment ring [20][9][32][4] halves = 11520 floats
#define WHH_OFF    12032    // float4 layout [16 k][8 c][16 h][4 q] = 8192
#define WAIH_OFF   20224    // raw [2][64 gate][16 k] = 2048
#define WAHH_OFF   22272    // 2048
#define W2S_OFF    24320    // [16][68] = 1088
#define WIH_OFF    25408    // float4 [8 c][16 h][4 q] = 512
#define BE_OFF     25920    // 512
#define PSB_OFF    26432    // prejob partials [12 w][64 j][4 g] = 3072
#define PSA_OFF    29504    // post-job partials [18 job][64 j][4 g] = 4608
#define OLDPS_OFF  34112    // [2 parity][64 j * 4 g] = 512
#define E1S_OFF    34624    // [4][64]
#define NC_OFF     34880    // [4][128]
#define B1S_OFF    35392    // 64
#define BAC_OFF    35456    // [2][64]
#define WGS_OFF    35584    // [8][16]
#define WOS_OFF    35712    // [8][16]
#define EHS_OFF    35840    // [4][16]
#define ECS_OFF    35904
#define AHS_OFF    35968    // [2][4][16]
#define ACS_OFF    36096
#define AIS_OFF    36224    // [4][16]
#define GSM_OFF    36288    // [4][8]
#define OSM_OFF    36320    // [4][8]
#define ERRH_OFF   36352    // [4][10]
#define B2S_OFF    36392
#define BGS_OFF    36408
#define BOS_OFF    36416
#define PRED_OFF   36424
#define THETA_OFF  36428
#define W01_OFF    36432    // m=0/m=1 weight frags [18 job][4 jt][32 lane] uint4 = 9216
#define SMEM_FLOATS 45648
#define SMEM_BYTES  (SMEM_FLOATS * 4)

__device__ __forceinline__ float tanhfast(float v) {
    float r;
    asm("tanh.approx.f32 %0, %1;" : "=f"(r) : "f"(v));
    return r;
}
__device__ __forceinline__ float sigf(float v) {
    return fmaf(tanhfast(0.5f * v), 0.5f, 0.5f);
}

__global__ void build_w1f(const float* __restrict__ W1) {
    int idx = blockIdx.x * 256 + threadIdx.x;
    if (idx >= W1F_U4) return;
    int lane = idx & 31;
    int jt   = (idx >> 5) & 3;
    int job  = idx >> 7;
    int r  = lane >> 2;
    int tg = lane & 3;
    float f[8];
    #pragma unroll
    for (int i = 0; i < 8; ++i) f[i] = 0.0f;
    if (job < 180) {
        int m  = job / 9;
        int kb = job - m * 9;
        int j0 = jt * 16;
        int kbase = kb * 16;
        const int dj[8] = {r, r, r + 8, r + 8, r, r, r + 8, r + 8};
        const int dc[8] = {2*tg, 2*tg+1, 2*tg, 2*tg+1, 2*tg+8, 2*tg+9, 2*tg+8, 2*tg+9};
        #pragma unroll
        for (int i = 0; i < 8; ++i) {
            int kc = kbase + dc[i];
            if (kc < 129) f[i] = W1[(j0 + dj[i]) * 2580 + m * 129 + kc];
        }
    }
    __half h[8];
    #pragma unroll
    for (int i = 0; i < 8; ++i) h[i] = __float2half(f[i]);
    uint4 u;
    u.x = *reinterpret_cast<unsigned int*>(&h[0]);
    u.y = *reinterpret_cast<unsigned int*>(&h[2]);
    u.z = *reinterpret_cast<unsigned int*>(&h[4]);
    u.w = *reinterpret_cast<unsigned int*>(&h[6]);
    g_W1f[idx] = u;
}

#define MMA16816(d, a, bx, by) \
    asm volatile("mma.sync.aligned.m16n8k16.row.col.f32.f16.f16.f32 " \
        "{%0,%1,%2,%3}, {%4,%5,%6,%7}, {%8,%9}, {%0,%1,%2,%3};" \
        : "+f"(d[0]), "+f"(d[1]), "+f"(d[2]), "+f"(d[3]) \
        : "r"(a.x), "r"(a.y), "r"(a.z), "r"(a.w), "r"(bx), "r"(by))

// 14 pre-barrier jobs (m>=2); results land 2 steps later (stored next
// iteration, reduced then into OLDPS for the step after).
__device__ __forceinline__ void prejobs(int sP, int w, int lane,
    const unsigned int* __restrict__ rhU,
    float (&d0)[4], float (&d1)[4], float (&d2)[4], float (&d3)[4])
{
    int J0 = 18 + w * 14;
    int m  = J0 / 9;
    int kb = J0 - m * 9;
    int slot = sP + m - 1;
    if (slot >= 20) slot -= 20;
    const uint4* __restrict__ wp = g_W1f + J0 * 128 + lane;
    #pragma unroll
    for (int it = 0; it < 14; ++it) {
        int bofs = ((slot * 9 + kb) * 32 + lane) * 2;
        unsigned int bx = rhU[bofs], by = rhU[bofs + 1];
        uint4 a0 = wp[it * 128];
        uint4 a1 = wp[it * 128 + 32];
        uint4 a2 = wp[it * 128 + 64];
        uint4 a3 = wp[it * 128 + 96];
        MMA16816(d0, a0, bx, by);
        MMA16816(d1, a1, bx, by);
        MMA16816(d2, a2, bx, by);
        MMA16816(d3, a3, bx, by);
        ++kb; if (kb == 9) { kb = 0; ++slot; if (slot == 20) slot = 0; }
    }
}

__device__ __forceinline__ void store_partials(float* __restrict__ base, int lane,
    const float (&d0)[4], const float (&d1)[4],
    const float (&d2)[4], const float (&d3)[4])
{
    int tg = lane & 3, gr = lane >> 2;
    if (tg < 2) {
        float* pb = base + 2 * tg;
        pb[(gr     ) * 4] = d0[0]; pb[(gr     ) * 4 + 1] = d0[1];
        pb[(gr +  8) * 4] = d0[2]; pb[(gr +  8) * 4 + 1] = d0[3];
        pb[(gr + 16) * 4] = d1[0]; pb[(gr + 16) * 4 + 1] = d1[1];
        pb[(gr + 24) * 4] = d1[2]; pb[(gr + 24) * 4 + 1] = d1[3];
        pb[(gr + 32) * 4] = d2[0]; pb[(gr + 32) * 4 + 1] = d2[1];
        pb[(gr + 40) * 4] = d2[2]; pb[(gr + 40) * 4 + 1] = d2[3];
        pb[(gr + 48) * 4] = d3[0]; pb[(gr + 48) * 4 + 1] = d3[1];
        pb[(gr + 56) * 4] = d3[2]; pb[(gr + 56) * 4 + 1] = d3[3];
    }
}

__global__ __launch_bounds__(NTHREADS, 1)
void mmoe_main(
    const float* __restrict__ x,      const float* __restrict__ pred0,
    const float* __restrict__ gate0,
    const float* __restrict__ W_ih,   const float* __restrict__ W_hh,
    const float* __restrict__ b_ih,   const float* __restrict__ b_hh,
    const float* __restrict__ W_o,    const float* __restrict__ b_o,
    const float* __restrict__ W1,     const float* __restrict__ b1,
    const float* __restrict__ W2,     const float* __restrict__ b2,
    const float* __restrict__ Wg,     const float* __restrict__ bg,
    const float* __restrict__ Wa_ih,  const float* __restrict__ Wa_hh,
    const float* __restrict__ ba_ih,  const float* __restrict__ ba_hh,
    float* __restrict__ out)
{
    extern __shared__ float sm[];
    __half* rh = reinterpret_cast<__half*>(&sm[RH_OFF]);
    const int tid = threadIdx.x;
    const int b0  = blockIdx.x * G;

    // ---------- init shared ----------
    if (tid < 512) sm[RING_OFF + tid] = 0.0f;
    for (int i = tid; i < 23040; i += NTHREADS) {
        int q = i & 3, ln = (i >> 2) & 31, kb = (i >> 7) % 9;
        bool is05 = (q == 0) && ((ln & 3) == 0) && (ln < 16) && (kb == 8);
        rh[i] = __float2half(is05 ? 0.5f : 0.0f);
    }
    for (int i = tid; i < 8192; i += NTHREADS) {
        int q = i & 3, h = (i >> 2) & 15, c = (i >> 6) & 7, k = i >> 9;
        sm[WHH_OFF + i] = W_hh[(c * 64 + q * 16 + h) * 16 + k];
    }
    {   // copy m=0/m=1 weight fragments to SMEM (jobs 0..17)
        uint4* w01 = reinterpret_cast<uint4*>(&sm[W01_OFF]);
        for (int i = tid; i < 18 * 128; i += NTHREADS) w01[i] = g_W1f[i];
    }
    for (int i = tid; i < 2048; i += NTHREADS) {
        sm[WAIH_OFF + i] = Wa_ih[i];
        sm[WAHH_OFF + i] = Wa_hh[i];
    }
    for (int i = tid; i < 1088; i += NTHREADS) {
        int j2 = i / 68, k = i - j2 * 68;
        sm[W2S_OFF + i] = (k < 64) ? W2[j2 * 64 + k] : 0.0f;
    }
    if (tid < 512) {
        int q = tid & 3, h = (tid >> 2) & 15, c = tid >> 6;
        int gidx = c * 64 + q * 16 + h;
        sm[WIH_OFF + tid] = W_ih[gidx];
        sm[BE_OFF + tid]  = b_ih[gidx] + b_hh[gidx];
    }
    if (tid < 256) {
        int jj = tid >> 2, gg = tid & 3;
        float sacc = 0.0f;
        for (int m = 1; m < 20; ++m) sacc += W1[jj * 2580 + m * 129 + 128];
        sm[OLDPS_OFF + jj * 4 + gg] = 0.5f * sacc;
    }
    if (tid < 128) {
        sm[BAC_OFF + tid] = ba_ih[tid] + ba_hh[tid];
        sm[WGS_OFF + tid] = Wg[tid];
        sm[WOS_OFF + tid] = W_o[tid];
        sm[AHS_OFF + tid] = 0.0f;
        sm[ACS_OFF + tid] = 0.0f;
    }
    if (tid < 64) { sm[B1S_OFF + tid] = b1[tid]; sm[EHS_OFF + tid] = 0.0f; sm[ECS_OFF + tid] = 0.0f; }
    if (tid < 40) sm[ERRH_OFF + tid] = 0.5f;
    if (tid < 32) sm[GSM_OFF + tid] = gate0[b0 * 8 + tid];
    if (tid < 16) sm[B2S_OFF + tid] = b2[tid];
    if (tid < 8)  { sm[BGS_OFF + tid] = bg[tid]; sm[BOS_OFF + tid] = b_o[tid]; }
    if (tid < 4)  sm[PRED_OFF + tid] = pred0[b0 + tid];
    __syncthreads();

    if (tid < 128) {
        // ====================== SMALL GROUP: warps 0-3 ======================
        int head = 0;
        for (int t = 0; t < NSTEP; ++t) {
            int s = head - 1; if (s < 0) s = 19;

            // ---- phase 2: experts; thread (c,h) handles all 4 g ----
            {
                int c = tid >> 4, h = tid & 15;
                int ch4 = (c * 16 + h) * 4;
                float be[4], wi[4];
                *reinterpret_cast<float4*>(be) = *(const float4*)&sm[BE_OFF + ch4];
                *reinterpret_cast<float4*>(wi) = *(const float4*)&sm[WIH_OFF + ch4];
                float z[4][4];
                #pragma unroll
                for (int g = 0; g < 4; ++g) {
                    float xv = __ldg(&x[(b0 + g) * NSTEP + t]);
                    #pragma unroll
                    for (int q = 0; q < 4; ++q) z[g][q] = be[q] + xv * wi[q];
                }
                #pragma unroll
                for (int kq = 0; kq < 4; ++kq) {
                    float ev[4][4];
                    #pragma unroll
                    for (int g = 0; g < 4; ++g)
                        *reinterpret_cast<float4*>(ev[g]) =
                            *(const float4*)&sm[EHS_OFF + g * 16 + kq * 4];
                    #pragma unroll
                    for (int kk = 0; kk < 4; ++kk) {
                        int k = kq * 4 + kk;
                        float wv[4];
                        *reinterpret_cast<float4*>(wv) =
                            *(const float4*)&sm[WHH_OFF + ((k * 8 + c) * 16 + h) * 4];
                        #pragma unroll
                        for (int g = 0; g < 4; ++g) {
                            float e = ev[g][kk];
                            z[g][0] += e * wv[0];
                            z[g][1] += e * wv[1];
                            z[g][2] += e * wv[2];
                            z[g][3] += e * wv[3];
                        }
                    }
                }
                int lane2 = ((h & 7) >> 1);
                int q2 = (h & 1) | ((h >> 3) << 1);
                #pragma unroll
                for (int g = 0; g < 4; ++g) {
                    float ec = sm[ECS_OFF + g * 16 + h];
                    float c2 = sigf(z[g][1]) * ec + sigf(z[g][0]) * tanhfast(z[g][2]);
                    float hn = sigf(z[g][3]) * tanhfast(c2);
                    sm[RING_OFF + g * 128 + c * 16 + h] = hn;
                    sm[NC_OFF + g * 128 + c * 16 + h] = c2;
                    rh[((s * 9 + c) * 32 + ((g << 2) | lane2)) * 4 + q2] = __float2half(hn);
                }
            }
            if (tid < 4) {
                float xv = x[(b0 + tid) * NSTEP + t];
                float e = xv - sm[PRED_OFF + tid];
                sm[ERRH_OFF + tid * 10 + (t % 10)] = e;
                rh[((s * 9 + 8) * 32 + (tid << 2)) * 4] = __float2half(e);
            }
            asm volatile("bar.sync 4, 512;" ::: "memory");   // ring slot s ready

            // ---- heads + theta (hidden under GEMM post-jobs) ----
            if (tid < 32) {
                int g = tid >> 3, c = tid & 7;
                float sacc = sm[BOS_OFF + c];
                const float* rr = &sm[RING_OFF + g * 128 + c * 16];
                #pragma unroll
                for (int h = 0; h < 16; ++h) sacc += rr[h] * sm[WOS_OFF + c * 16 + h];
                sm[OSM_OFF + g * 8 + c] = sacc;
            } else if (tid < 36) {
                int g = tid - 32;
                float sacc = 0.0f;
                #pragma unroll
                for (int i2 = 0; i2 < 10; ++i2) sacc += fabsf(sm[ERRH_OFF + g * 10 + i2]);
                sm[THETA_OFF + g] = fminf(0.25f * sacc, 1.0f);
            }
            asm volatile("bar.sync 5, 512;" ::: "memory");   // E1S published

            if (tid < 64) {
                // ---- MLP2 ----
                int g = tid >> 4, j2 = tid & 15;
                {
                    const float4* e4 = reinterpret_cast<const float4*>(&sm[E1S_OFF + g * 64]);
                    const float4* w4 = reinterpret_cast<const float4*>(&sm[W2S_OFF + j2 * 68]);
                    float a[4] = {0.f, 0.f, 0.f, 0.f};
                    #pragma unroll
                    for (int kq = 0; kq < 16; ++kq) {
                        float4 e = e4[kq];
                        float4 w = w4[kq];
                        a[kq & 3] += e.x * w.x + e.y * w.y + e.z * w.z + e.w * w.w;
                    }
                    float sacc = sm[B2S_OFF + j2] + (a[0] + a[1]) + (a[2] + a[3]);
                    sm[AIS_OFF + g * 16 + j2] = fmaxf(sacc, 0.0f);
                }
                __syncwarp();
                // ---- agent: 2 fused LSTM layers ----
                int h = j2;
                #pragma unroll
                for (int l = 0; l < 2; ++l) {
                    const float* inp = (l == 0) ? &sm[AIS_OFF + g * 16]
                                                : &sm[AHS_OFF + g * 16];
                    const float* hp  = &sm[AHS_OFF + l * 64 + g * 16];
                    float iv[16], hv[16];
                    #pragma unroll
                    for (int kq = 0; kq < 4; ++kq) {
                        *reinterpret_cast<float4*>(&iv[kq * 4]) =
                            *(const float4*)&inp[kq * 4];
                        *reinterpret_cast<float4*>(&hv[kq * 4]) =
                            *(const float4*)&hp[kq * 4];
                    }
                    float z[4];
                    #pragma unroll
                    for (int q = 0; q < 4; ++q) {
                        const float4* wi4 = (const float4*)&sm[WAIH_OFF + l * 1024 + (q * 16 + h) * 16];
                        const float4* wh4 = (const float4*)&sm[WAHH_OFF + l * 1024 + (q * 16 + h) * 16];
                        float za = sm[BAC_OFF + l * 64 + q * 16 + h], zb = 0.0f;
                        #pragma unroll
                        for (int kq = 0; kq < 4; ++kq) {
                            float4 wi = wi4[kq], wh = wh4[kq];
                            za += iv[kq*4] * wi.x + iv[kq*4+1] * wi.y
                                + iv[kq*4+2] * wi.z + iv[kq*4+3] * wi.w;
                            zb += hv[kq*4] * wh.x + hv[kq*4+1] * wh.y
                                + hv[kq*4+2] * wh.z + hv[kq*4+3] * wh.w;
                        }
                        z[q] = za + zb;
                    }
                    float c2 = sigf(z[1]) * sm[ACS_OFF + l * 64 + g * 16 + h]
                             + sigf(z[0]) * tanhfast(z[2]);
                    float hn = sigf(z[3]) * tanhfast(c2);
                    sm[ACS_OFF + l * 64 + g * 16 + h] = c2;
                    sm[AHS_OFF + l * 64 + g * 16 + h] = hn;
                    __syncwarp();
                }
            }
            asm volatile("bar.sync 1, 128;" ::: "memory");

            // ---- gate logits + softmax + blend + pred + eh2/ec2 (one warp) ----
            if (tid < 32) {
                int g = tid >> 3, c = tid & 7;
                const float* a1p = &sm[AHS_OFF + 64 + g * 16];
                const float* wg  = &sm[WGS_OFF + c * 16];
                float za = sm[BGS_OFF + c], zb = 0.0f;
                #pragma unroll
                for (int k = 0; k < 8; ++k) {
                    za += a1p[2 * k] * wg[2 * k];
                    zb += a1p[2 * k + 1] * wg[2 * k + 1];
                }
                float zv = za + zb;
                float mx = zv;
                #pragma unroll
                for (int d = 1; d < 8; d <<= 1)
                    mx = fmaxf(mx, __shfl_xor_sync(0xffffffffu, mx, d));
                float ex = __expf(zv - mx);
                float ssum = ex;
                #pragma unroll
                for (int d = 1; d < 8; d <<= 1)
                    ssum += __shfl_xor_sync(0xffffffffu, ssum, d);
                float th = sm[THETA_OFF + g];
                float gf = ex * __fdividef(th, ssum)
                         + sm[GSM_OFF + g * 8 + c] * (1.0f - th);
                sm[GSM_OFF + g * 8 + c] = gf;
                float pv = gf * sm[OSM_OFF + g * 8 + c];
                #pragma unroll
                for (int d = 1; d < 8; d <<= 1)
                    pv += __shfl_xor_sync(0xffffffffu, pv, d);
                if (c == 0) {
                    sm[PRED_OFF + g] = pv;
                    out[(b0 + g) * NSTEP + t] = pv;
                }
                // eh2/ec2: lane (g,c) computes h = 2c, 2c+1
                const float* rr = &sm[RING_OFF + g * 128];
                const float* nc = &sm[NC_OFF + g * 128];
                float se0 = 0.f, se1 = 0.f, sc0 = 0.f, sc1 = 0.f;
                #pragma unroll
                for (int cc = 0; cc < 8; ++cc) {
                    float gfb = __shfl_sync(0xffffffffu, gf, (g << 3) | cc);
                    se0 += gfb * rr[cc * 16 + 2 * c];
                    se1 += gfb * rr[cc * 16 + 2 * c + 1];
                    sc0 += gfb * nc[cc * 16 + 2 * c];
                    sc1 += gfb * nc[cc * 16 + 2 * c + 1];
                }
                sm[EHS_OFF + g * 16 + 2 * c]     = se0;
                sm[EHS_OFF + g * 16 + 2 * c + 1] = se1;
                sm[ECS_OFF + g * 16 + 2 * c]     = sc0;
                sm[ECS_OFF + g * 16 + 2 * c + 1] = sc1;
            }
            asm volatile("bar.sync 1, 128;" ::: "memory");

            head = s;
        }
    } else {
        // ====================== GEMM GROUP: warps 4-15 ======================
        const int w    = (tid >> 5) - 4;   // 0..11
        const int lane = tid & 31;
        const unsigned int* __restrict__ rhU =
            reinterpret_cast<const unsigned int*>(rh);
        const uint4* __restrict__ w01 =
            reinterpret_cast<const uint4*>(&sm[W01_OFF]);

        float d0[4] = {0,0,0,0}, d1[4] = {0,0,0,0};
        float d2[4] = {0,0,0,0}, d3[4] = {0,0,0,0};
        prejobs(19, w, lane, rhU, d0, d1, d2, d3);   // m>=2 jobs landing at t=1

        int head = 0;
        for (int t = 0; t < NSTEP; ++t) {
            int s = head - 1; if (s < 0) s = 19;

            // prejob partials -> PSB BEFORE bar4 (overlaps phase 2)
            store_partials(&sm[PSB_OFF + w * 256], lane, d0, d1, d2, d3);

            asm volatile("bar.sync 4, 512;" ::: "memory");   // slot s ready

            float e0[4], e1[4], e2[4], e3[4];
            if (w < 9) {
                // m=1 job (kb=w), slot s -> row 1 of step t+1
                #pragma unroll
                for (int i = 0; i < 4; ++i) { e0[i]=0.f; e1[i]=0.f; e2[i]=0.f; e3[i]=0.f; }
                int bofs = ((s * 9 + w) * 32 + lane) * 2;
                unsigned int bx = rhU[bofs], by = rhU[bofs + 1];
                const uint4* wq = w01 + (9 + w) * 128 + lane;
                uint4 a0 = wq[0], a1 = wq[32], a2 = wq[64], a3 = wq[96];
                MMA16816(e0, a0, bx, by);
                MMA16816(e1, a1, bx, by);
                MMA16816(e2, a2, bx, by);
                MMA16816(e3, a3, bx, by);
                store_partials(&sm[PSA_OFF + w * 256], lane, e0, e1, e2, e3);
            }
            if (w >= 3) {
                // m=0 job (kb=w-3), slot s -> row 0 of step t (E1S now)
                int kb0 = w - 3;
                #pragma unroll
                for (int i = 0; i < 4; ++i) { e0[i]=0.f; e1[i]=0.f; e2[i]=0.f; e3[i]=0.f; }
                int bofs = ((s * 9 + kb0) * 32 + lane) * 2;
                unsigned int bx = rhU[bofs], by = rhU[bofs + 1];
                const uint4* wq = w01 + kb0 * 128 + lane;
                uint4 a0 = wq[0], a1 = wq[32], a2 = wq[64], a3 = wq[96];
                MMA16816(e0, a0, bx, by);
                MMA16816(e1, a1, bx, by);
                MMA16816(e2, a2, bx, by);
                MMA16816(e3, a3, bx, by);
                store_partials(&sm[PSA_OFF + (9 + kb0) * 256], lane, e0, e1, e2, e3);
            }
            asm volatile("bar.sync 2, 384;" ::: "memory");
            // reduce: OLDPS (step t+1) and E1S (step t)
            {
                int r = tid - 128;
                if (r < 256) {
                    int jr = r >> 2, gr = r & 3;
                    float sOld = 0.0f;
                    #pragma unroll
                    for (int c = 0; c < 12; ++c)
                        sOld += sm[PSB_OFF + (c * 64 + jr) * 4 + gr];
                    #pragma unroll
                    for (int c = 0; c < 9; ++c)
                        sOld += sm[PSA_OFF + (c * 64 + jr) * 4 + gr];
                    sm[OLDPS_OFF + ((t + 1) & 1) * 256 + jr * 4 + gr] = sOld;
                    float sE = sm[OLDPS_OFF + (t & 1) * 256 + jr * 4 + gr] + sm[B1S_OFF + jr];
                    #pragma unroll
                    for (int c = 9; c < 18; ++c)
                        sE += sm[PSA_OFF + (c * 64 + jr) * 4 + gr];
                    sm[E1S_OFF + gr * 64 + jr] = fmaxf(sE, 0.0f);
                }
            }
            asm volatile("bar.sync 5, 512;" ::: "memory");   // publish E1S

            #pragma unroll
            for (int i = 0; i < 4; ++i) { d0[i] = 0.f; d1[i] = 0.f; d2[i] = 0.f; d3[i] = 0.f; }
            if (t < NSTEP - 1) {
                int s1 = s - 1; if (s1 < 0) s1 = 19;
                prejobs(s1, w, lane, rhU, d0, d1, d2, d3);
            }
            head = s;
        }
    }
}

extern "C" void kernel_launch(void* const* d_in, const int* in_sizes, int n_in,
                              void* d_out, int out_size) {
    const float* x      = (const float*)d_in[0];
    const float* pred0  = (const float*)d_in[1];
    const float* gate0  = (const float*)d_in[2];
    const float* W_ih   = (const float*)d_in[3];
    const float* W_hh   = (const float*)d_in[4];
    const float* b_ih   = (const float*)d_in[5];
    const float* b_hh   = (const float*)d_in[6];
    const float* W_o    = (const float*)d_in[7];
    const float* b_o    = (const float*)d_in[8];
    const float* W1     = (const float*)d_in[9];
    const float* b1     = (const float*)d_in[10];
    const float* W2     = (const float*)d_in[11];
    const float* b2     = (const float*)d_in[12];
    const float* Wg     = (const float*)d_in[13];
    const float* bg     = (const float*)d_in[14];
    const float* Wa_ih  = (const float*)d_in[15];
    const float* Wa_hh  = (const float*)d_in[16];
    const float* ba_ih  = (const float*)d_in[17];
    const float* ba_hh  = (const float*)d_in[18];
    float* out = (float*)d_out;

    cudaFuncSetAttribute(mmoe_main, cudaFuncAttributeMaxDynamicSharedMemorySize, SMEM_BYTES);

    build_w1f<<<(W1F_U4 + 255) / 256, 256>>>(W1);
    mmoe_main<<<NCTA, NTHREADS, SMEM_BYTES>>>(
        x, pred0, gate0, W_ih, W_hh, b_ih, b_hh, W_o, b_o,
        W1, b1, W2, b2, Wg, bg, Wa_ih, Wa_hh, ba_ih, ba_hh, out);
}